// round 4
// baseline (speedup 1.0000x reference)
#include <cuda_runtime.h>
#include <math.h>

// Problem constants (fixed by the dataset)
#define Bn 2048
#define Dn 1024
#define Hn 2048
#define En 16
#define Wn 4
#define Rn 8
#define MAXK 4
#define CANDMAX 16
#define NG (En * Wn)      // 64 groups
#define SCALE_C 1.0f

// ---------------- scratch (device globals; no allocation allowed) -----------
__device__ float g_hpre[Bn * Hn];     // 16 MB
__device__ float g_outpre[Bn * Dn];   // 8 MB
__device__ float g_cand_val[Bn * CANDMAX];
__device__ unsigned long long g_pack[Bn];   // candidate expert ids, 4-bit nibbles
__device__ int   g_assigned_idx[Bn * MAXK];
__device__ float g_assigned_w[Bn * MAXK];
__device__ int   g_widx[Bn * MAXK];
__device__ int   g_hist[NG];
__device__ int   g_goff[NG + 1];
__device__ unsigned g_glist[Bn * MAXK];     // packed b*4+s
__device__ float g_scratch[(size_t)Bn * MAXK * Dn];  // 32 MB

// ---------------- output layout (flattened concat of the returned tuple) ----
struct Outs {
    float* z;      // [B, D]
    float* probs;  // [B, E]
    float* mask;   // [B, E]
    float* aidx;   // [B, k]
    float* aw;     // [B, k]
    float* chr;    // [1]
    float* ev_e;   // [k*B]
    float* ev_a;   // [k*B]
};

__host__ __device__ __forceinline__ Outs make_outs(float* o, int k) {
    Outs s;
    s.z     = o; o += Bn * Dn;
    s.probs = o; o += Bn * En;
    s.mask  = o; o += Bn * En;
    s.aidx  = o; o += Bn * k;
    s.aw    = o; o += Bn * k;
    s.chr   = o; o += 1;
    s.ev_e  = o; o += (size_t)k * Bn;
    s.ev_a  = o;
    return s;
}

__device__ __forceinline__ float warp_reduce(float v) {
    #pragma unroll
    for (int off = 16; off; off >>= 1) v += __shfl_xor_sync(0xffffffffu, v, off);
    return v;
}

__device__ __forceinline__ float silu_f(float x) {
    return x / (1.0f + expf(-x));
}

__device__ __forceinline__ unsigned f2tf32(float f) {
    unsigned u;
    asm volatile("cvt.rna.tf32.f32 %0, %1;" : "=r"(u) : "f"(f));
    return u;
}

__device__ __forceinline__ void mma_tf32(float* d, const unsigned* a, const unsigned* b) {
    asm volatile(
        "mma.sync.aligned.m16n8k8.row.col.f32.tf32.tf32.f32 "
        "{%0,%1,%2,%3}, {%4,%5,%6,%7}, {%8,%9}, {%0,%1,%2,%3};"
        : "+f"(d[0]), "+f"(d[1]), "+f"(d[2]), "+f"(d[3])
        : "r"(a[0]), "r"(a[1]), "r"(a[2]), "r"(a[3]), "r"(b[0]), "r"(b[1]));
}

// =====================================================================
// Kernel 1: logits -> softmax -> probs, top-cand_k candidates (packed),
//           default-init of routed output regions. One warp per token.
// =====================================================================
__global__ void logits_topk_kernel(const float* __restrict__ z,
                                   const float* __restrict__ proto,
                                   const float* __restrict__ ebias,
                                   const int* __restrict__ topk_p,
                                   const int* __restrict__ ban_p,
                                   const float* __restrict__ tau_p,
                                   const float* __restrict__ eps_p,
                                   float* __restrict__ d_out) {
    int gwarp = (blockIdx.x * blockDim.x + threadIdx.x) >> 5;
    int lane  = threadIdx.x & 31;
    if (gwarp >= Bn) return;
    const int b = gwarp;
    const float* zr = z + (size_t)b * Dn;

    float acc[En];
    #pragma unroll
    for (int e = 0; e < En; e++) acc[e] = 0.0f;

    for (int d = lane; d < Dn; d += 32) {
        float zv = zr[d];
        #pragma unroll
        for (int e = 0; e < En; e++) acc[e] += zv * proto[e * Dn + d];
    }
    #pragma unroll
    for (int e = 0; e < En; e++) acc[e] = warp_reduce(acc[e]);

    if (lane != 0) return;

    int k = *topk_p; if (k > En) k = En; if (k > MAXK) k = MAXK; if (k < 1) k = 1;
    int cand_k = 4 * k; if (cand_k < k) cand_k = k; if (cand_k > En) cand_k = En;
    int ban = *ban_p;
    float inv_tau = 1.0f / fmaxf(*tau_p, 1e-6f);
    float eps = *eps_p;

    float lg[En];
    float mx = -1e30f;
    #pragma unroll
    for (int e = 0; e < En; e++) {
        float v = acc[e] * inv_tau + ebias[e];
        if (e == ban) v = -1e9f;
        lg[e] = v;
        mx = fmaxf(mx, v);
    }
    float sum = 0.0f;
    #pragma unroll
    for (int e = 0; e < En; e++) { lg[e] = expf(lg[e] - mx); sum += lg[e]; }
    float inv = 1.0f / sum;

    Outs O = make_outs(d_out, k);
    float pr[En];
    #pragma unroll
    for (int e = 0; e < En; e++) {
        pr[e] = (1.0f - eps) * (lg[e] * inv) + eps / (float)En;
        O.probs[b * En + e] = pr[e];
        O.mask[b * En + e]  = 0.0f;
    }

    // top-cand_k selection, ties -> lowest index first (strict >)
    bool used[En];
    #pragma unroll
    for (int e = 0; e < En; e++) used[e] = false;
    unsigned long long pk = 0ull;
    for (int j = 0; j < cand_k; j++) {
        float bv = -1e30f; int bi = 0;
        for (int e = 0; e < En; e++) {
            if (!used[e] && pr[e] > bv) { bv = pr[e]; bi = e; }
        }
        used[bi] = true;
        g_cand_val[b * CANDMAX + j] = bv;
        pk |= ((unsigned long long)bi) << (4 * j);
    }
    g_pack[b] = pk;

    for (int s = 0; s < k; s++) {
        g_assigned_idx[b * MAXK + s] = -1;
        g_assigned_w[b * MAXK + s]   = 0.0f;
        O.aidx[b * k + s] = -1.0f;
        O.aw[b * k + s]   = 0.0f;
        O.ev_e[s * Bn + b] = -1.0f;
        O.ev_a[s * Bn + b] = -1.0f;
    }
}

// =====================================================================
// Kernel 2: batched greedy capacity router. Single warp, 32 tokens/batch.
// Decisions depend only on the monotone closed-expert set; commit the
// prefix before the earliest capacity violation each iteration.
// =====================================================================
__global__ void route_kernel(const int* __restrict__ topk_p,
                             const int* __restrict__ cap_p,
                             float* __restrict__ d_out) {
    const int lane = threadIdx.x;
    int k = *topk_p; if (k > En) k = En; if (k > MAXK) k = MAXK; if (k < 1) k = 1;
    int cand_k = 4 * k; if (cand_k < k) cand_k = k; if (cand_k > En) cand_k = En;
    int cap_lim = *cap_p; if (cap_lim < 1) cap_lim = 1;

    // zero the group histogram for the akdot kernel
    if (lane < 32) { g_hist[lane] = 0; g_hist[lane + 32] = 0; }

    Outs O = make_outs(d_out, k);

    int cap = 0;            // lane < En holds cap[lane]
    unsigned closed = 0;    // uniform 16-bit closed-expert mask
    int hits = 0;

    int t0 = 0;
    while (t0 < Bn) {
        const int t = t0 + lane;
        const bool has = (t < Bn);
        unsigned long long pk = has ? g_pack[t] : 0ull;

        unsigned take = 0;
        unsigned slotcand = 0;
        int nslots = 0;
        int myhits = 0;
        if (has) {
            for (int j = 0; j < cand_k; j++) {
                int e = (int)((pk >> (4 * j)) & 15ull);
                if (!((closed >> e) & 1u) && nslots < k) {
                    take |= (1u << e);
                    slotcand |= ((unsigned)j) << (4 * nslots);
                    if (j > 0) myhits++;
                    nslots++;
                }
            }
        }

        unsigned mybits = 0;
        #pragma unroll
        for (int e = 0; e < En; e++) {
            unsigned bb = __ballot_sync(0xffffffffu, (take >> e) & 1u);
            if (lane == e) mybits = bb;
        }
        int cnt = __popc(mybits);

        bool viol = (lane < En) && !((closed >> lane) & 1u) && (cap + cnt > cap_lim);
        unsigned vm = __ballot_sync(0xffffffffu, viol);
        int pstar = 32;
        if (vm) {
            int myp = 32;
            if (viol) {
                int rem = cap_lim - cap;
                unsigned m = mybits;
                for (int i = 0; i < rem; i++) m &= m - 1;
                myp = __ffs(m) - 1;
            }
            #pragma unroll
            for (int off = 16; off; off >>= 1) {
                int o = __shfl_xor_sync(0xffffffffu, myp, off);
                myp = min(myp, o);
            }
            pstar = myp;
        }

        unsigned commit_prefix = (pstar >= 32) ? 0xffffffffu : ((1u << pstar) - 1u);
        if (lane < En) cap += __popc(mybits & commit_prefix);

        if (has && lane < pstar) {
            for (int s = 0; s < nslots; s++) {
                int j = (int)((slotcand >> (4 * s)) & 15u);
                int e = (int)((pk >> (4 * j)) & 15ull);
                float v = g_cand_val[t * CANDMAX + j];
                g_assigned_idx[t * MAXK + s] = e;
                g_assigned_w[t * MAXK + s]   = v;
                O.aidx[t * k + s] = (float)e;
                O.aw[t * k + s]   = v;
                O.ev_e[s * Bn + t] = (float)e;
                O.mask[t * En + e] = 1.0f;
            }
            hits += myhits;
        }

        closed = __ballot_sync(0xffffffffu, (lane < En) && (cap >= cap_lim)) & 0xffffu;
        t0 += pstar;
    }

    #pragma unroll
    for (int off = 16; off; off >>= 1) hits += __shfl_xor_sync(0xffffffffu, hits, off);
    if (lane == 0) O.chr[0] = (float)hits / (float)(Bn * k);
}

// =====================================================================
// Kernel 3: adapter-key argmax for assigned slots only + group histogram.
// One block (128 thr = 4 warps) per token; warp w handles key w.
// =====================================================================
__global__ void __launch_bounds__(128)
akdot_kernel(const float* __restrict__ z,
             const float* __restrict__ ak,
             const int* __restrict__ topk_p,
             float* __restrict__ d_out) {
    __shared__ float s_z[Dn];
    __shared__ float s_sc[Wn];

    const int b = blockIdx.x;
    const int tid = threadIdx.x;
    const int lane = tid & 31;
    const int warp = tid >> 5;   // 0..3 = key index

    int k = *topk_p; if (k > En) k = En; if (k > MAXK) k = MAXK; if (k < 1) k = 1;
    Outs O = make_outs(d_out, k);

    for (int i = tid; i < Dn / 4; i += 128)
        *(float4*)(&s_z[i * 4]) = ((const float4*)(z + (size_t)b * Dn))[i];
    __syncthreads();

    for (int s = 0; s < k; s++) {
        int e = g_assigned_idx[b * MAXK + s];
        if (e >= 0) {
            const float4* akr = (const float4*)(ak + (size_t)(e * Wn + warp) * Dn);
            float p = 0.0f;
            #pragma unroll
            for (int i = 0; i < Dn / 128; i++) {
                float4 a = akr[lane + i * 32];
                float4 zz = *(const float4*)(&s_z[(lane + i * 32) * 4]);
                p += a.x * zz.x + a.y * zz.y + a.z * zz.z + a.w * zz.w;
            }
            p = warp_reduce(p);
            if (lane == 0) s_sc[warp] = p;
        }
        __syncthreads();
        if (tid == 0 && e >= 0) {
            float bv = s_sc[0]; int bi = 0;
            #pragma unroll
            for (int w2 = 1; w2 < Wn; w2++)
                if (s_sc[w2] > bv) { bv = s_sc[w2]; bi = w2; }
            g_widx[b * MAXK + s] = bi;
            O.ev_a[s * Bn + b] = (float)bi;
            atomicAdd(&g_hist[e * Wn + bi], 1);
        }
        __syncthreads();
    }
}

// =====================================================================
// Kernel 4: scan group histogram + scatter slot records into group lists.
// Single block. List order within a group is irrelevant (each slot writes
// its own scratch region) so shared-atomic placement is fine.
// =====================================================================
__global__ void __launch_bounds__(256)
scan_scatter_kernel(const int* __restrict__ topk_p) {
    __shared__ int s_off[NG + 1];
    __shared__ int s_cur[NG];
    const int tid = threadIdx.x;
    int k = *topk_p; if (k > En) k = En; if (k > MAXK) k = MAXK; if (k < 1) k = 1;

    if (tid == 0) {
        int acc = 0;
        for (int g2 = 0; g2 < NG; g2++) { s_off[g2] = acc; acc += g_hist[g2]; }
        s_off[NG] = acc;
    }
    __syncthreads();
    if (tid < NG) s_cur[tid] = 0;
    if (tid <= NG) g_goff[tid] = s_off[tid];
    __syncthreads();

    for (int idx = tid; idx < Bn * k; idx += 256) {
        int b = idx / k;
        int s = idx % k;
        int e = g_assigned_idx[b * MAXK + s];
        if (e >= 0) {
            int g2 = e * Wn + g_widx[b * MAXK + s];
            int p = atomicAdd(&s_cur[g2], 1);
            g_glist[s_off[g2] + p] = (unsigned)(b * 4 + s);
        }
    }
}

// =====================================================================
// Kernel 5/6: TF32 tensor-core GEMM, double-buffered SMEM pipeline.
// =====================================================================
#define TBM 128
#define TBN 128
#define TBK 32
#define LDP 36
#define GPITCH ((TBM + TBN) * LDP)

template <int ACT>
__global__ void __launch_bounds__(256, 1)
gemm_tf32_kernel(const float* __restrict__ A, const float* __restrict__ Wt,
                 const float* __restrict__ bias, float* __restrict__ C,
                 int M, int N, int K) {
    extern __shared__ unsigned smem_u[];

    const int bx = blockIdx.x;
    const int by = blockIdx.y;
    const int tid = threadIdx.x;
    const int warp = tid >> 5;
    const int lane = tid & 31;
    const int g  = lane >> 2;
    const int tg = lane & 3;

    const int wm = (warp & 3) * 32;
    const int wn = (warp >> 2) * 64;

    const int r0 = tid >> 3;
    const int fq = tid & 7;

    const float* Aptr = A  + (size_t)(by * TBM) * K;
    const float* Bptr = Wt + (size_t)(bx * TBN) * K;

    float acc[2][8][4];
    #pragma unroll
    for (int i = 0; i < 2; i++)
        #pragma unroll
        for (int j = 0; j < 8; j++)
            #pragma unroll
            for (int c = 0; c < 4; c++) acc[i][j][c] = 0.0f;

    float4 ra[4], rb[4];
    #pragma unroll
    for (int i = 0; i < 4; i++) {
        ra[i] = *(const float4*)(Aptr + (size_t)(r0 + 32 * i) * K + fq * 4);
        rb[i] = *(const float4*)(Bptr + (size_t)(r0 + 32 * i) * K + fq * 4);
    }
    {
        unsigned* As0 = smem_u;
        unsigned* Bs0 = smem_u + TBM * LDP;
        #pragma unroll
        for (int i = 0; i < 4; i++) {
            uint4 ua, ub;
            ua.x = f2tf32(ra[i].x); ua.y = f2tf32(ra[i].y);
            ua.z = f2tf32(ra[i].z); ua.w = f2tf32(ra[i].w);
            ub.x = f2tf32(rb[i].x); ub.y = f2tf32(rb[i].y);
            ub.z = f2tf32(rb[i].z); ub.w = f2tf32(rb[i].w);
            *(uint4*)(&As0[(r0 + 32 * i) * LDP + fq * 4]) = ua;
            *(uint4*)(&Bs0[(r0 + 32 * i) * LDP + fq * 4]) = ub;
        }
    }
    __syncthreads();

    const int KIT = K / TBK;
    for (int kt = 0; kt < KIT; kt++) {
        const int cur = kt & 1;
        const bool more = (kt + 1 < KIT);
        unsigned* AsC = smem_u + cur * GPITCH;
        unsigned* BsC = AsC + TBM * LDP;

        if (more) {
            int k0 = (kt + 1) * TBK;
            #pragma unroll
            for (int i = 0; i < 4; i++) {
                ra[i] = *(const float4*)(Aptr + (size_t)(r0 + 32 * i) * K + k0 + fq * 4);
                rb[i] = *(const float4*)(Bptr + (size_t)(r0 + 32 * i) * K + k0 + fq * 4);
            }
        }

        #pragma unroll
        for (int kk = 0; kk < 4; kk++) {
            unsigned afr[2][4];
            #pragma unroll
            for (int mi = 0; mi < 2; mi++) {
                int row = wm + mi * 16 + g;
                afr[mi][0] = AsC[row * LDP + kk * 8 + tg];
                afr[mi][1] = AsC[(row + 8) * LDP + kk * 8 + tg];
                afr[mi][2] = AsC[row * LDP + kk * 8 + tg + 4];
                afr[mi][3] = AsC[(row + 8) * LDP + kk * 8 + tg + 4];
            }
            unsigned bfr[8][2];
            #pragma unroll
            for (int ni = 0; ni < 8; ni++) {
                int col = wn + ni * 8 + g;
                bfr[ni][0] = BsC[col * LDP + kk * 8 + tg];
                bfr[ni][1] = BsC[col * LDP + kk * 8 + tg + 4];
            }
            #pragma unroll
            for (int mi = 0; mi < 2; mi++)
                #pragma unroll
                for (int ni = 0; ni < 8; ni++)
                    mma_tf32(acc[mi][ni], afr[mi], bfr[ni]);
        }

        if (more) {
            unsigned* AsN = smem_u + (1 - cur) * GPITCH;
            unsigned* BsN = AsN + TBM * LDP;
            #pragma unroll
            for (int i = 0; i < 4; i++) {
                uint4 ua, ub;
                ua.x = f2tf32(ra[i].x); ua.y = f2tf32(ra[i].y);
                ua.z = f2tf32(ra[i].z); ua.w = f2tf32(ra[i].w);
                ub.x = f2tf32(rb[i].x); ub.y = f2tf32(rb[i].y);
                ub.z = f2tf32(rb[i].z); ub.w = f2tf32(rb[i].w);
                *(uint4*)(&AsN[(r0 + 32 * i) * LDP + fq * 4]) = ua;
                *(uint4*)(&BsN[(r0 + 32 * i) * LDP + fq * 4]) = ub;
            }
        }
        __syncthreads();
    }

    #pragma unroll
    for (int mi = 0; mi < 2; mi++) {
        int row0 = by * TBM + wm + mi * 16 + g;
        #pragma unroll
        for (int ni = 0; ni < 8; ni++) {
            int col = bx * TBN + wn + ni * 8 + 2 * tg;
            float b0 = bias[col], b1 = bias[col + 1];
            float v0 = acc[mi][ni][0] + b0;
            float v1 = acc[mi][ni][1] + b1;
            float v2 = acc[mi][ni][2] + b0;
            float v3 = acc[mi][ni][3] + b1;
            if (ACT) { v0 = silu_f(v0); v1 = silu_f(v1); v2 = silu_f(v2); v3 = silu_f(v3); }
            *(float2*)(&C[(size_t)row0 * N + col])       = make_float2(v0, v1);
            *(float2*)(&C[(size_t)(row0 + 8) * N + col]) = make_float2(v2, v3);
        }
    }
}

// =====================================================================
// Kernel 7: grouped LoRA apply. grid (64 groups, 16 chunks), 256 threads.
// ALL weights of the (e,w) group staged in SMEM once (192 KB), then
// tokens processed warp-per-token. Writes w*(out_pre+d2) per slot to
// scratch (deterministic: each slot owns its region).
// SMEM layout (floats): A1s[8*1024] | B1t[8*2048] | A2s[8*2048] | B2t[8*1024]
// =====================================================================
#define TOK_CHUNK 16

__global__ void __launch_bounds__(256, 1)
group_apply_kernel(const float* __restrict__ z,
                   const float* __restrict__ a1, const float* __restrict__ b1,
                   const float* __restrict__ a2, const float* __restrict__ b2) {
    extern __shared__ float sm[];
    float* A1s = sm;                 // [r][d]  8*1024
    float* B1t = sm + 8192;          // [r][h]  8*2048
    float* A2s = sm + 8192 + 16384;  // [r][h]  8*2048
    float* B2t = sm + 8192 + 32768;  // [r][d]  8*1024

    const int g = blockIdx.x;
    const int g0 = g_goff[g];
    const int cnt = g_goff[g + 1] - g0;
    if (cnt == 0 || (int)blockIdx.y * TOK_CHUNK >= cnt) return;

    const int tid = threadIdx.x;
    const int lane = tid & 31;
    const int warp = tid >> 5;

    // ---- stage weights ----
    const float4* A1g = (const float4*)(a1 + (size_t)g * Rn * Dn);
    const float4* A2g = (const float4*)(a2 + (size_t)g * Rn * Hn);
    #pragma unroll
    for (int i = tid; i < 2048; i += 256) ((float4*)A1s)[i] = A1g[i];
    #pragma unroll
    for (int i = tid; i < 4096; i += 256) ((float4*)A2s)[i] = A2g[i];
    // B1 [h][r] -> B1t [r][h]
    const float* b1g = b1 + (size_t)g * Hn * Rn;
    for (int h = tid; h < Hn; h += 256) {
        float4 v0 = *(const float4*)(b1g + h * Rn);
        float4 v1 = *(const float4*)(b1g + h * Rn + 4);
        B1t[0 * Hn + h] = v0.x; B1t[1 * Hn + h] = v0.y;
        B1t[2 * Hn + h] = v0.z; B1t[3 * Hn + h] = v0.w;
        B1t[4 * Hn + h] = v1.x; B1t[5 * Hn + h] = v1.y;
        B1t[6 * Hn + h] = v1.z; B1t[7 * Hn + h] = v1.w;
    }
    // B2 [d][r] -> B2t [r][d]
    const float* b2g = b2 + (size_t)g * Dn * Rn;
    for (int d = tid; d < Dn; d += 256) {
        float4 v0 = *(const float4*)(b2g + d * Rn);
        float4 v1 = *(const float4*)(b2g + d * Rn + 4);
        B2t[0 * Dn + d] = v0.x; B2t[1 * Dn + d] = v0.y;
        B2t[2 * Dn + d] = v0.z; B2t[3 * Dn + d] = v0.w;
        B2t[4 * Dn + d] = v1.x; B2t[5 * Dn + d] = v1.y;
        B2t[6 * Dn + d] = v1.z; B2t[7 * Dn + d] = v1.w;
    }
    __syncthreads();

    for (int c = blockIdx.y; c * TOK_CHUNK < cnt; c += gridDim.y) {
        const int nbase = g0 + c * TOK_CHUNK;
        const int n = min(TOK_CHUNK, cnt - c * TOK_CHUNK);

        for (int rr = 0; rr < TOK_CHUNK / 8; rr++) {
            const int ti = rr * 8 + warp;
            if (ti < n) {
                const unsigned rec = g_glist[nbase + ti];
                const int b = rec >> 2;
                const int s = rec & 3;

                // ---- t1[r] = z . A1[r,:] ----
                const float4* zr = (const float4*)(z + (size_t)b * Dn);
                float t1[Rn];
                #pragma unroll
                for (int r = 0; r < Rn; r++) t1[r] = 0.0f;
                #pragma unroll
                for (int i = 0; i < 8; i++) {
                    const int c4 = lane + i * 32;   // float4 column
                    float4 zv = zr[c4];
                    #pragma unroll
                    for (int r = 0; r < Rn; r++) {
                        float4 av = ((const float4*)(A1s + r * Dn))[c4];
                        t1[r] += zv.x * av.x + zv.y * av.y + zv.z * av.z + zv.w * av.w;
                    }
                }
                #pragma unroll
                for (int r = 0; r < Rn; r++) t1[r] = warp_reduce(t1[r]);

                // ---- stream H: h = silu(hpre + t1.B1t); t2[r] += h*A2s ----
                const float* hpr = g_hpre + (size_t)b * Hn;
                float t2[Rn];
                #pragma unroll
                for (int r = 0; r < Rn; r++) t2[r] = 0.0f;
                for (int h = lane; h < Hn; h += 32) {
                    float d1 = 0.0f;
                    #pragma unroll
                    for (int r = 0; r < Rn; r++) d1 += t1[r] * B1t[r * Hn + h];
                    float hv = silu_f(hpr[h] + d1 * SCALE_C);
                    #pragma unroll
                    for (int r = 0; r < Rn; r++) t2[r] += hv * A2s[r * Hn + h];
                }
                #pragma unroll
                for (int r = 0; r < Rn; r++) t2[r] = warp_reduce(t2[r]);

                // ---- d2 & scratch write ----
                const float wgt = g_assigned_w[b * MAXK + s];
                const float* opr = g_outpre + (size_t)b * Dn;
                float* scr = g_scratch + ((size_t)(b * MAXK + s)) * Dn;
                for (int d = lane; d < Dn; d += 32) {
                    float d2 = 0.0f;
                    #pragma unroll
                    for (int r = 0; r < Rn; r++) d2 += t2[r] * B2t[r * Dn + d];
                    scr[d] = wgt * (opr[d] + d2 * SCALE_C);
                }
            }
        }
    }
}

// =====================================================================
// Kernel 8: final combine  O.z = z + sum_s scratch[b,s] (valid slots).
// =====================================================================
__global__ void __launch_bounds__(256)
combine_kernel(const float* __restrict__ z,
               const int* __restrict__ topk_p,
               float* __restrict__ d_out) {
    const int b = blockIdx.x;
    const int tid = threadIdx.x;
    int k = *topk_p; if (k > En) k = En; if (k > MAXK) k = MAXK; if (k < 1) k = 1;
    Outs O = make_outs(d_out, k);

    int vmask = 0;
    #pragma unroll
    for (int s = 0; s < MAXK; s++)
        if (s < k && g_assigned_idx[b * MAXK + s] >= 0) vmask |= (1 << s);

    const float4* zr = (const float4*)(z + (size_t)b * Dn);
    float4* outr = (float4*)(O.z + (size_t)b * Dn);
    for (int i = tid; i < Dn / 4; i += 256) {
        float4 acc = zr[i];
        #pragma unroll
        for (int s = 0; s < MAXK; s++) {
            if (vmask & (1 << s)) {
                float4 v = ((const float4*)(g_scratch + ((size_t)(b * MAXK + s)) * Dn))[i];
                acc.x += v.x; acc.y += v.y; acc.z += v.z; acc.w += v.w;
            }
        }
        outr[i] = acc;
    }
}

// =====================================================================
// launch
// =====================================================================
extern "C" void kernel_launch(void* const* d_in, const int* in_sizes, int n_in,
                              void* d_out, int out_size) {
    const float* z     = (const float*)d_in[0];
    const int*   topk  = (const int*)  d_in[1];
    const int*   cap   = (const int*)  d_in[2];
    const int*   ban   = (const int*)  d_in[3];
    const float* tau   = (const float*)d_in[4];
    const float* eps   = (const float*)d_in[5];
    const float* fc1w  = (const float*)d_in[6];
    const float* fc1b  = (const float*)d_in[7];
    const float* fc2w  = (const float*)d_in[8];
    const float* fc2b  = (const float*)d_in[9];
    const float* proto = (const float*)d_in[10];
    const float* ak    = (const float*)d_in[11];
    const float* ebias = (const float*)d_in[12];
    const float* a1    = (const float*)d_in[13];
    const float* b1    = (const float*)d_in[14];
    const float* a2    = (const float*)d_in[15];
    const float* b2    = (const float*)d_in[16];
    float* out = (float*)d_out;

    float *hpre_ptr = nullptr, *outpre_ptr = nullptr;
    cudaGetSymbolAddress((void**)&hpre_ptr, g_hpre);
    cudaGetSymbolAddress((void**)&outpre_ptr, g_outpre);

    const int gemm_smem = 2 * (TBM + TBN) * LDP * sizeof(unsigned);  // 73728
    cudaFuncSetAttribute(gemm_tf32_kernel<1>,
                         cudaFuncAttributeMaxDynamicSharedMemorySize, gemm_smem);
    cudaFuncSetAttribute(gemm_tf32_kernel<0>,
                         cudaFuncAttributeMaxDynamicSharedMemorySize, gemm_smem);
    const int grp_smem = (8192 + 16384 + 16384 + 8192) * sizeof(float);  // 196608
    cudaFuncSetAttribute(group_apply_kernel,
                         cudaFuncAttributeMaxDynamicSharedMemorySize, grp_smem);

    // 1) logits / probs / candidates / output defaults
    logits_topk_kernel<<<Bn / 4, 128>>>(z, proto, ebias, topk, ban, tau, eps, out);

    // 2) batched greedy capacity routing (single warp)
    route_kernel<<<1, 32>>>(topk, cap, out);

    // 3) adapter-key argmax (assigned slots only) + histogram
    akdot_kernel<<<Bn, 128>>>(z, ak, topk, out);

    // 4) scan + scatter group lists
    scan_scatter_kernel<<<1, 256>>>(topk);

    // 5) h_pre = silu(z @ fc1_w^T + fc1_b)   [B,H]
    gemm_tf32_kernel<1><<<dim3(Hn / TBN, Bn / TBM), 256, gemm_smem>>>(
        z, fc1w, fc1b, hpre_ptr, Bn, Hn, Dn);

    // 6) out_pre = h_pre @ fc2_w^T + fc2_b   [B,D]
    gemm_tf32_kernel<0><<<dim3(Dn / TBN, Bn / TBM), 256, gemm_smem>>>(
        hpre_ptr, fc2w, fc2b, outpre_ptr, Bn, Dn, Hn);

    // 7) grouped LoRA apply (weights staged once per (e,w) group)
    group_apply_kernel<<<dim3(NG, 16), 256, grp_smem>>>(z, a1, b1, a2, b2);

    // 8) final combine
    combine_kernel<<<Bn, 256>>>(z, topk, out);
}

// round 6
// speedup vs baseline: 1.4248x; 1.4248x over previous
#include <cuda_runtime.h>
#include <math.h>

// Problem constants (fixed by the dataset)
#define Bn 2048
#define Dn 1024
#define Hn 2048
#define En 16
#define Wn 4
#define Rn 8
#define MAXK 4
#define CANDMAX 16
#define SCALE_C 1.0f

// ---------------- scratch (device globals; no allocation allowed) -----------
__device__ float g_hpre[Bn * Hn];     // 16 MB
__device__ float g_outpre[Bn * Dn];   // 8 MB
__device__ float g_cand_val[Bn * CANDMAX];
__device__ unsigned long long g_pack[Bn];   // candidate expert ids, 4-bit nibbles
__device__ int   g_assigned_idx[Bn * MAXK];
__device__ float g_assigned_w[Bn * MAXK];

// ---------------- output layout (flattened concat of the returned tuple) ----
struct Outs {
    float* z;      // [B, D]
    float* probs;  // [B, E]
    float* mask;   // [B, E]
    float* aidx;   // [B, k]
    float* aw;     // [B, k]
    float* chr;    // [1]
    float* ev_e;   // [k*B]
    float* ev_a;   // [k*B]
};

__host__ __device__ __forceinline__ Outs make_outs(float* o, int k) {
    Outs s;
    s.z     = o; o += Bn * Dn;
    s.probs = o; o += Bn * En;
    s.mask  = o; o += Bn * En;
    s.aidx  = o; o += Bn * k;
    s.aw    = o; o += Bn * k;
    s.chr   = o; o += 1;
    s.ev_e  = o; o += (size_t)k * Bn;
    s.ev_a  = o;
    return s;
}

__device__ __forceinline__ float warp_reduce(float v) {
    #pragma unroll
    for (int off = 16; off; off >>= 1) v += __shfl_xor_sync(0xffffffffu, v, off);
    return v;
}

__device__ __forceinline__ float silu_f(float x) {
    return x / (1.0f + expf(-x));
}

__device__ __forceinline__ unsigned f2tf32(float f) {
    unsigned u;
    asm volatile("cvt.rna.tf32.f32 %0, %1;" : "=r"(u) : "f"(f));
    return u;
}

__device__ __forceinline__ void mma_tf32(float* d, const unsigned* a, const unsigned* b) {
    asm volatile(
        "mma.sync.aligned.m16n8k8.row.col.f32.tf32.tf32.f32 "
        "{%0,%1,%2,%3}, {%4,%5,%6,%7}, {%8,%9}, {%0,%1,%2,%3};"
        : "+f"(d[0]), "+f"(d[1]), "+f"(d[2]), "+f"(d[3])
        : "r"(a[0]), "r"(a[1]), "r"(a[2]), "r"(a[3]), "r"(b[0]), "r"(b[1]));
}

// =====================================================================
// Side work A: logits -> softmax -> probs, top-cand_k candidates
// (packed), default-init of routed output regions. One warp per token.
// =====================================================================
__device__ void logits_body(int b, int lane,
                            const float* __restrict__ z,
                            const float* __restrict__ proto,
                            const float* __restrict__ ebias,
                            const int* __restrict__ topk_p,
                            const int* __restrict__ ban_p,
                            const float* __restrict__ tau_p,
                            const float* __restrict__ eps_p,
                            float* __restrict__ d_out) {
    const float* zr = z + (size_t)b * Dn;

    float acc[En];
    #pragma unroll
    for (int e = 0; e < En; e++) acc[e] = 0.0f;

    for (int d = lane; d < Dn; d += 32) {
        float zv = zr[d];
        #pragma unroll
        for (int e = 0; e < En; e++) acc[e] += zv * proto[e * Dn + d];
    }
    #pragma unroll
    for (int e = 0; e < En; e++) acc[e] = warp_reduce(acc[e]);

    if (lane != 0) return;

    int k = *topk_p; if (k > En) k = En; if (k > MAXK) k = MAXK; if (k < 1) k = 1;
    int cand_k = 4 * k; if (cand_k < k) cand_k = k; if (cand_k > En) cand_k = En;
    int ban = *ban_p;
    float inv_tau = 1.0f / fmaxf(*tau_p, 1e-6f);
    float eps = *eps_p;

    float lg[En];
    float mx = -1e30f;
    #pragma unroll
    for (int e = 0; e < En; e++) {
        float v = acc[e] * inv_tau + ebias[e];
        if (e == ban) v = -1e9f;
        lg[e] = v;
        mx = fmaxf(mx, v);
    }
    float sum = 0.0f;
    #pragma unroll
    for (int e = 0; e < En; e++) { lg[e] = expf(lg[e] - mx); sum += lg[e]; }
    float inv = 1.0f / sum;

    Outs O = make_outs(d_out, k);
    float pr[En];
    #pragma unroll
    for (int e = 0; e < En; e++) {
        pr[e] = (1.0f - eps) * (lg[e] * inv) + eps / (float)En;
        O.probs[b * En + e] = pr[e];
        O.mask[b * En + e]  = 0.0f;
    }

    // top-cand_k selection, ties -> lowest index first (strict >)
    bool used[En];
    #pragma unroll
    for (int e = 0; e < En; e++) used[e] = false;
    unsigned long long pk = 0ull;
    for (int j = 0; j < cand_k; j++) {
        float bv = -1e30f; int bi = 0;
        for (int e = 0; e < En; e++) {
            if (!used[e] && pr[e] > bv) { bv = pr[e]; bi = e; }
        }
        used[bi] = true;
        g_cand_val[b * CANDMAX + j] = bv;
        pk |= ((unsigned long long)bi) << (4 * j);
    }
    g_pack[b] = pk;

    for (int s = 0; s < k; s++) {
        g_assigned_idx[b * MAXK + s] = -1;
        g_assigned_w[b * MAXK + s]   = 0.0f;
        O.aidx[b * k + s] = -1.0f;
        O.aw[b * k + s]   = 0.0f;
        O.ev_e[s * Bn + b] = -1.0f;
        O.ev_a[s * Bn + b] = -1.0f;
    }
}

// =====================================================================
// Side work B: batched greedy capacity router. Single warp, 32 tok/iter.
// =====================================================================
__device__ void route_body(int lane,
                           const int* __restrict__ topk_p,
                           const int* __restrict__ cap_p,
                           float* __restrict__ d_out) {
    int k = *topk_p; if (k > En) k = En; if (k > MAXK) k = MAXK; if (k < 1) k = 1;
    int cand_k = 4 * k; if (cand_k < k) cand_k = k; if (cand_k > En) cand_k = En;
    int cap_lim = *cap_p; if (cap_lim < 1) cap_lim = 1;

    Outs O = make_outs(d_out, k);

    int cap = 0;            // lane < En holds cap[lane]
    unsigned closed = 0;
    int hits = 0;

    int t0 = 0;
    while (t0 < Bn) {
        const int t = t0 + lane;
        const bool has = (t < Bn);
        unsigned long long pk = has ? g_pack[t] : 0ull;

        unsigned take = 0;
        unsigned slotcand = 0;
        int nslots = 0;
        int myhits = 0;
        if (has) {
            for (int j = 0; j < cand_k; j++) {
                int e = (int)((pk >> (4 * j)) & 15ull);
                if (!((closed >> e) & 1u) && nslots < k) {
                    take |= (1u << e);
                    slotcand |= ((unsigned)j) << (4 * nslots);
                    if (j > 0) myhits++;
                    nslots++;
                }
            }
        }

        unsigned mybits = 0;
        #pragma unroll
        for (int e = 0; e < En; e++) {
            unsigned bb = __ballot_sync(0xffffffffu, (take >> e) & 1u);
            if (lane == e) mybits = bb;
        }
        int cnt = __popc(mybits);

        bool viol = (lane < En) && !((closed >> lane) & 1u) && (cap + cnt > cap_lim);
        unsigned vm = __ballot_sync(0xffffffffu, viol);
        int pstar = 32;
        if (vm) {
            int myp = 32;
            if (viol) {
                int rem = cap_lim - cap;
                unsigned m = mybits;
                for (int i = 0; i < rem; i++) m &= m - 1;
                myp = __ffs(m) - 1;
            }
            #pragma unroll
            for (int off = 16; off; off >>= 1) {
                int o = __shfl_xor_sync(0xffffffffu, myp, off);
                myp = min(myp, o);
            }
            pstar = myp;
        }

        unsigned commit_prefix = (pstar >= 32) ? 0xffffffffu : ((1u << pstar) - 1u);
        if (lane < En) cap += __popc(mybits & commit_prefix);

        if (has && lane < pstar) {
            for (int s = 0; s < nslots; s++) {
                int j = (int)((slotcand >> (4 * s)) & 15u);
                int e = (int)((pk >> (4 * j)) & 15ull);
                float v = g_cand_val[t * CANDMAX + j];
                g_assigned_idx[t * MAXK + s] = e;
                g_assigned_w[t * MAXK + s]   = v;
                O.aidx[t * k + s] = (float)e;
                O.aw[t * k + s]   = v;
                O.ev_e[s * Bn + t] = (float)e;
                O.mask[t * En + e] = 1.0f;
            }
            hits += myhits;
        }

        closed = __ballot_sync(0xffffffffu, (lane < En) && (cap >= cap_lim)) & 0xffffu;
        t0 += pstar;
    }

    #pragma unroll
    for (int off = 16; off; off >>= 1) hits += __shfl_xor_sync(0xffffffffu, hits, off);
    if (lane == 0) O.chr[0] = (float)hits / (float)(Bn * k);
}

// =====================================================================
// Fused TF32 GEMM + side work. 512 threads = 16 warps (4 per SMSP).
// GEMM (blocks bx < NX): C[m,n] = act( sum_k A[m,k]*Wt[n,k] + bias[n] ),
//   block tile 128x128x32, warp tile 32x32 (4x4 warp grid), m16n8k8.tf32.
//   SMEM: [m][k] / [n][k] row-major, LDP=36 padding (conflict-free frag
//   loads: bank = (4*row + k) mod 32). Double-buffered; STS.128 staging.
// Side blocks (bx >= NX): SIDE=1 -> logits (16 warps = 16 tokens/block),
//                         SIDE=2 -> route (block (NX,0) warp 0 only).
// =====================================================================
#define TBM 128
#define TBN 128
#define TBK 32
#define LDP 36
#define GPITCH ((TBM + TBN) * LDP)

template <int ACT, int SIDE, int NX>
__global__ void __launch_bounds__(512, 1)
gemm_fused_kernel(const float* __restrict__ A, const float* __restrict__ Wt,
                  const float* __restrict__ bias, float* __restrict__ C,
                  int M, int N, int K,
                  const float* __restrict__ z, const float* __restrict__ proto,
                  const float* __restrict__ ebias,
                  const int* __restrict__ topk_p, const int* __restrict__ ban_p,
                  const float* __restrict__ tau_p, const float* __restrict__ eps_p,
                  const int* __restrict__ cap_p,
                  float* __restrict__ d_out) {
    const int bx = blockIdx.x;
    const int by = blockIdx.y;
    const int tid = threadIdx.x;
    const int warp = tid >> 5;   // 0..15
    const int lane = tid & 31;

    if (bx >= NX) {
        if (SIDE == 1) {
            int blk = (bx - NX) * gridDim.y + by;
            int b = blk * 16 + warp;
            if (b < Bn)
                logits_body(b, lane, z, proto, ebias, topk_p, ban_p, tau_p, eps_p, d_out);
        } else if (SIDE == 2) {
            if (by == 0 && warp == 0)
                route_body(lane, topk_p, cap_p, d_out);
        }
        return;
    }

    extern __shared__ unsigned smem_u[];

    const int g  = lane >> 2;   // 0..7
    const int tg = lane & 3;    // 0..3
    const int wq  = warp & 3;   // warp m index (0..3)
    const int wn4 = warp >> 2;  // warp n index (0..3)

    // staging: thread handles rows r0, r0+64; k chunk fq (float4)
    const int r0 = tid >> 3;        // 0..63
    const int fq = tid & 7;         // 0..7

    const float* Aptr = A  + (size_t)(by * TBM) * K;
    const float* Bptr = Wt + (size_t)(bx * TBN) * K;

    float acc[2][4][4];
    #pragma unroll
    for (int i = 0; i < 2; i++)
        #pragma unroll
        for (int j = 0; j < 4; j++)
            #pragma unroll
            for (int c = 0; c < 4; c++) acc[i][j][c] = 0.0f;

    float4 ra[2], rb[2];
    #pragma unroll
    for (int i = 0; i < 2; i++) {
        ra[i] = *(const float4*)(Aptr + (size_t)(r0 + 64 * i) * K + fq * 4);
        rb[i] = *(const float4*)(Bptr + (size_t)(r0 + 64 * i) * K + fq * 4);
    }

    auto stage_store = [&](int buf) {
        unsigned* As = smem_u + buf * GPITCH;
        unsigned* Bs = As + TBM * LDP;
        #pragma unroll
        for (int i = 0; i < 2; i++) {
            uint4 ua, ub;
            ua.x = f2tf32(ra[i].x); ua.y = f2tf32(ra[i].y);
            ua.z = f2tf32(ra[i].z); ua.w = f2tf32(ra[i].w);
            ub.x = f2tf32(rb[i].x); ub.y = f2tf32(rb[i].y);
            ub.z = f2tf32(rb[i].z); ub.w = f2tf32(rb[i].w);
            *(uint4*)(&As[(r0 + 64 * i) * LDP + fq * 4]) = ua;
            *(uint4*)(&Bs[(r0 + 64 * i) * LDP + fq * 4]) = ub;
        }
    };

    stage_store(0);
    __syncthreads();

    const int KIT = K / TBK;
    for (int kt = 0; kt < KIT; kt++) {
        const int cur = kt & 1;
        const bool more = (kt + 1 < KIT);
        const unsigned* AsC = smem_u + cur * GPITCH;
        const unsigned* BsC = AsC + TBM * LDP;

        if (more) {
            int k0 = (kt + 1) * TBK;
            #pragma unroll
            for (int i = 0; i < 2; i++) {
                ra[i] = *(const float4*)(Aptr + (size_t)(r0 + 64 * i) * K + k0 + fq * 4);
                rb[i] = *(const float4*)(Bptr + (size_t)(r0 + 64 * i) * K + k0 + fq * 4);
            }
        }

        #pragma unroll
        for (int kk = 0; kk < 4; kk++) {
            unsigned afr[2][4];
            #pragma unroll
            for (int mi = 0; mi < 2; mi++) {
                int row = wq * 32 + mi * 16 + g;
                afr[mi][0] = AsC[row * LDP + kk * 8 + tg];
                afr[mi][1] = AsC[(row + 8) * LDP + kk * 8 + tg];
                afr[mi][2] = AsC[row * LDP + kk * 8 + tg + 4];
                afr[mi][3] = AsC[(row + 8) * LDP + kk * 8 + tg + 4];
            }
            unsigned bfr[4][2];
            #pragma unroll
            for (int ni = 0; ni < 4; ni++) {
                int col = wn4 * 32 + ni * 8 + g;
                bfr[ni][0] = BsC[col * LDP + kk * 8 + tg];
                bfr[ni][1] = BsC[col * LDP + kk * 8 + tg + 4];
            }
            #pragma unroll
            for (int mi = 0; mi < 2; mi++)
                #pragma unroll
                for (int ni = 0; ni < 4; ni++)
                    mma_tf32(acc[mi][ni], afr[mi], bfr[ni]);
        }

        if (more) stage_store(1 - cur);
        __syncthreads();
    }

    // epilogue
    #pragma unroll
    for (int mi = 0; mi < 2; mi++) {
        int row0 = by * TBM + wq * 32 + mi * 16 + g;
        #pragma unroll
        for (int ni = 0; ni < 4; ni++) {
            int col = bx * TBN + wn4 * 32 + ni * 8 + 2 * tg;
            float b0 = bias[col], b1 = bias[col + 1];
            float v0 = acc[mi][ni][0] + b0;
            float v1 = acc[mi][ni][1] + b1;
            float v2 = acc[mi][ni][2] + b0;
            float v3 = acc[mi][ni][3] + b1;
            if (ACT) { v0 = silu_f(v0); v1 = silu_f(v1); v2 = silu_f(v2); v3 = silu_f(v3); }
            *(float2*)(&C[(size_t)row0 * N + col])       = make_float2(v0, v1);
            *(float2*)(&C[(size_t)(row0 + 8) * N + col]) = make_float2(v2, v3);
        }
    }
}

// =====================================================================
// Adapter selection + LoRA apply + final output (round-3 version).
// =====================================================================
__global__ void __launch_bounds__(256)
adapter_kernel(const float* __restrict__ z,
               const float* __restrict__ ak,
               const float* __restrict__ a1, const float* __restrict__ b1,
               const float* __restrict__ a2, const float* __restrict__ b2,
               const int* __restrict__ topk_p,
               float* __restrict__ d_out) {
    __shared__ float s_z[Dn];
    __shared__ float s_hp[Hn];
    __shared__ float s_h[2][Hn];
    __shared__ float s_t1[2][Rn];
    __shared__ float s_t2[2][Rn];
    __shared__ float s_sc[2][Wn];
    __shared__ int   s_base[2];
    __shared__ float s_wgt[2];
    __shared__ int   s_valid[2];

    const int b = blockIdx.x;
    const int tid = threadIdx.x;
    const int lane = tid & 31;
    const int warp = tid >> 5;
    const int group = warp >> 2;
    const int wig = warp & 3;
    const int gt = tid & 127;

    int k = *topk_p; if (k > En) k = En; if (k > MAXK) k = MAXK; if (k < 1) k = 1;
    Outs O = make_outs(d_out, k);

    for (int i = tid; i < Dn; i += 256) s_z[i] = z[(size_t)b * Dn + i];
    for (int i = tid; i < Hn; i += 256) s_hp[i] = g_hpre[(size_t)b * Hn + i];

    float opre[Dn / 256];
    float accd[Dn / 256];
    #pragma unroll
    for (int i = 0; i < Dn / 256; i++) {
        opre[i] = g_outpre[(size_t)b * Dn + tid + i * 256];
        accd[i] = 0.0f;
    }
    __syncthreads();

    for (int s0 = 0; s0 < k; s0 += 2) {
        const int sA = s0 + group;
        const bool act = (sA < k);
        int e = -1;
        float wgt = 0.0f;
        if (act) {
            e   = g_assigned_idx[b * MAXK + sA];
            wgt = g_assigned_w[b * MAXK + sA];
        }
        const bool valid = act && (e >= 0);

        if (valid) {
            const float* akr = ak + (size_t)(e * Wn + wig) * Dn;
            float p0 = 0.0f, p1 = 0.0f;
            for (int d = lane; d < Dn; d += 64) {
                p0 += s_z[d] * akr[d];
                p1 += s_z[d + 32] * akr[d + 32];
            }
            float p = warp_reduce(p0 + p1);
            if (lane == 0) s_sc[group][wig] = p;
        }
        __syncthreads();

        if (gt == 0) {
            if (valid) {
                float bv = s_sc[group][0]; int bi = 0;
                #pragma unroll
                for (int w2 = 1; w2 < Wn; w2++)
                    if (s_sc[group][w2] > bv) { bv = s_sc[group][w2]; bi = w2; }
                s_base[group] = e * Wn + bi;
                s_wgt[group] = wgt;
                s_valid[group] = 1;
                O.ev_a[sA * Bn + b] = (float)bi;
            } else {
                s_valid[group] = 0;
            }
        }
        __syncthreads();

        const int base = s_base[group];

        if (valid) {
            const float* A1r0 = a1 + ((size_t)base * Rn + 2 * wig) * Dn;
            const float* A1r1 = A1r0 + Dn;
            float q0 = 0.0f, q1 = 0.0f;
            for (int d = lane; d < Dn; d += 32) {
                float zv = s_z[d];
                q0 += zv * A1r0[d];
                q1 += zv * A1r1[d];
            }
            q0 = warp_reduce(q0);
            q1 = warp_reduce(q1);
            if (lane == 0) { s_t1[group][2 * wig] = q0; s_t1[group][2 * wig + 1] = q1; }
        }
        __syncthreads();

        if (valid) {
            float t1r[Rn];
            #pragma unroll
            for (int r = 0; r < Rn; r++) t1r[r] = s_t1[group][r];
            for (int h = gt; h < Hn; h += 128) {
                const float* B1r = b1 + ((size_t)base * Hn + h) * Rn;
                float d1 = 0.0f;
                #pragma unroll
                for (int r = 0; r < Rn; r++) d1 += t1r[r] * B1r[r];
                s_h[group][h] = silu_f(s_hp[h] + d1 * SCALE_C);
            }
        }
        __syncthreads();

        if (valid) {
            const float* A2r0 = a2 + ((size_t)base * Rn + 2 * wig) * Hn;
            const float* A2r1 = A2r0 + Hn;
            float q0 = 0.0f, q1 = 0.0f;
            for (int h2 = lane; h2 < Hn; h2 += 32) {
                float hv = s_h[group][h2];
                q0 += hv * A2r0[h2];
                q1 += hv * A2r1[h2];
            }
            q0 = warp_reduce(q0);
            q1 = warp_reduce(q1);
            if (lane == 0) { s_t2[group][2 * wig] = q0; s_t2[group][2 * wig + 1] = q1; }
        }
        __syncthreads();

        #pragma unroll
        for (int gg = 0; gg < 2; gg++) {
            if (s_valid[gg]) {
                const int bs = s_base[gg];
                const float wg = s_wgt[gg];
                float t2r[Rn];
                #pragma unroll
                for (int r = 0; r < Rn; r++) t2r[r] = s_t2[gg][r];
                #pragma unroll
                for (int i = 0; i < Dn / 256; i++) {
                    int d = tid + i * 256;
                    const float* B2r = b2 + ((size_t)bs * Dn + d) * Rn;
                    float d2 = 0.0f;
                    #pragma unroll
                    for (int r = 0; r < Rn; r++) d2 += t2r[r] * B2r[r];
                    accd[i] += wg * (opre[i] + d2 * SCALE_C);
                }
            }
        }
        __syncthreads();
    }

    #pragma unroll
    for (int i = 0; i < Dn / 256; i++) {
        int d = tid + i * 256;
        O.z[(size_t)b * Dn + d] = s_z[d] + accd[i];
    }
}

// =====================================================================
// launch
// =====================================================================
extern "C" void kernel_launch(void* const* d_in, const int* in_sizes, int n_in,
                              void* d_out, int out_size) {
    const float* z     = (const float*)d_in[0];
    const int*   topk  = (const int*)  d_in[1];
    const int*   cap   = (const int*)  d_in[2];
    const int*   ban   = (const int*)  d_in[3];
    const float* tau   = (const float*)d_in[4];
    const float* eps   = (const float*)d_in[5];
    const float* fc1w  = (const float*)d_in[6];
    const float* fc1b  = (const float*)d_in[7];
    const float* fc2w  = (const float*)d_in[8];
    const float* fc2b  = (const float*)d_in[9];
    const float* proto = (const float*)d_in[10];
    const float* ak    = (const float*)d_in[11];
    const float* ebias = (const float*)d_in[12];
    const float* a1    = (const float*)d_in[13];
    const float* b1    = (const float*)d_in[14];
    const float* a2    = (const float*)d_in[15];
    const float* b2    = (const float*)d_in[16];
    float* out = (float*)d_out;

    float *hpre_ptr = nullptr, *outpre_ptr = nullptr;
    cudaGetSymbolAddress((void**)&hpre_ptr, g_hpre);
    cudaGetSymbolAddress((void**)&outpre_ptr, g_outpre);

    const int gemm_smem = 2 * GPITCH * sizeof(unsigned);  // 73728
    cudaFuncSetAttribute((const void*)gemm_fused_kernel<1, 1, 16>,
                         cudaFuncAttributeMaxDynamicSharedMemorySize, gemm_smem);
    cudaFuncSetAttribute((const void*)gemm_fused_kernel<0, 2, 8>,
                         cudaFuncAttributeMaxDynamicSharedMemorySize, gemm_smem);

    // 1) h_pre = silu(z @ fc1_w^T + fc1_b)  [B,H] + logits/topk side blocks
    //    grid: 16 gemm cols + 8 side cols (128 side blocks x 16 warps = 2048)
    gemm_fused_kernel<1, 1, 16><<<dim3(24, 16), 512, gemm_smem>>>(
        z, fc1w, fc1b, hpre_ptr, Bn, Hn, Dn,
        z, proto, ebias, topk, ban, tau, eps, cap, out);

    // 2) out_pre = h_pre @ fc2_w^T + fc2_b  [B,D] + router side block
    gemm_fused_kernel<0, 2, 8><<<dim3(9, 16), 512, gemm_smem>>>(
        hpre_ptr, fc2w, fc2b, outpre_ptr, Bn, Dn, Hn,
        z, proto, ebias, topk, ban, tau, eps, cap, out);

    // 3) adapter select + LoRA deltas + final combine
    adapter_kernel<<<Bn, 256>>>(z, ak, a1, b1, a2, b2, topk, out);
}

// round 7
// speedup vs baseline: 1.5618x; 1.0961x over previous
#include <cuda_runtime.h>
#include <math.h>

// Problem constants (fixed by the dataset)
#define Bn 2048
#define Dn 1024
#define Hn 2048
#define En 16
#define Wn 4
#define Rn 8
#define MAXK 4
#define CANDMAX 16
#define SCALE_C 1.0f

// ---------------- scratch (device globals; no allocation allowed) -----------
__device__ float g_hpre[Bn * Hn];     // 16 MB
__device__ float g_outpre[Bn * Dn];   // 8 MB
__device__ float g_cand_val[Bn * CANDMAX];
__device__ unsigned long long g_pack[Bn];   // candidate expert ids, 4-bit nibbles
__device__ int   g_assigned_idx[Bn * MAXK];
__device__ float g_assigned_w[Bn * MAXK];

// ---------------- output layout (flattened concat of the returned tuple) ----
struct Outs {
    float* z;      // [B, D]
    float* probs;  // [B, E]
    float* mask;   // [B, E]
    float* aidx;   // [B, k]
    float* aw;     // [B, k]
    float* chr;    // [1]
    float* ev_e;   // [k*B]
    float* ev_a;   // [k*B]
};

__host__ __device__ __forceinline__ Outs make_outs(float* o, int k) {
    Outs s;
    s.z     = o; o += Bn * Dn;
    s.probs = o; o += Bn * En;
    s.mask  = o; o += Bn * En;
    s.aidx  = o; o += Bn * k;
    s.aw    = o; o += Bn * k;
    s.chr   = o; o += 1;
    s.ev_e  = o; o += (size_t)k * Bn;
    s.ev_a  = o;
    return s;
}

__device__ __forceinline__ float warp_reduce(float v) {
    #pragma unroll
    for (int off = 16; off; off >>= 1) v += __shfl_xor_sync(0xffffffffu, v, off);
    return v;
}

__device__ __forceinline__ float silu_f(float x) {
    return x / (1.0f + expf(-x));
}

// pack two fp32 into bf16x2 (lo = first arg, hi = second; RN rounding)
__device__ __forceinline__ unsigned pack_bf16(float lo, float hi) {
    unsigned r;
    asm("cvt.rn.bf16x2.f32 %0, %1, %2;" : "=r"(r) : "f"(hi), "f"(lo));
    return r;
}

__device__ __forceinline__ void mma_bf16(float* d, const unsigned* a, const unsigned* b) {
    asm volatile(
        "mma.sync.aligned.m16n8k16.row.col.f32.bf16.bf16.f32 "
        "{%0,%1,%2,%3}, {%4,%5,%6,%7}, {%8,%9}, {%0,%1,%2,%3};"
        : "+f"(d[0]), "+f"(d[1]), "+f"(d[2]), "+f"(d[3])
        : "r"(a[0]), "r"(a[1]), "r"(a[2]), "r"(a[3]), "r"(b[0]), "r"(b[1]));
}

// =====================================================================
// Side work A: logits -> softmax -> probs, top-cand_k candidates
// (packed), default-init of routed output regions. One warp per token.
// =====================================================================
__device__ void logits_body(int b, int lane,
                            const float* __restrict__ z,
                            const float* __restrict__ proto,
                            const float* __restrict__ ebias,
                            const int* __restrict__ topk_p,
                            const int* __restrict__ ban_p,
                            const float* __restrict__ tau_p,
                            const float* __restrict__ eps_p,
                            float* __restrict__ d_out) {
    const float* zr = z + (size_t)b * Dn;

    float acc[En];
    #pragma unroll
    for (int e = 0; e < En; e++) acc[e] = 0.0f;

    for (int d = lane; d < Dn; d += 32) {
        float zv = zr[d];
        #pragma unroll
        for (int e = 0; e < En; e++) acc[e] += zv * proto[e * Dn + d];
    }
    #pragma unroll
    for (int e = 0; e < En; e++) acc[e] = warp_reduce(acc[e]);

    if (lane != 0) return;

    int k = *topk_p; if (k > En) k = En; if (k > MAXK) k = MAXK; if (k < 1) k = 1;
    int cand_k = 4 * k; if (cand_k < k) cand_k = k; if (cand_k > En) cand_k = En;
    int ban = *ban_p;
    float inv_tau = 1.0f / fmaxf(*tau_p, 1e-6f);
    float eps = *eps_p;

    float lg[En];
    float mx = -1e30f;
    #pragma unroll
    for (int e = 0; e < En; e++) {
        float v = acc[e] * inv_tau + ebias[e];
        if (e == ban) v = -1e9f;
        lg[e] = v;
        mx = fmaxf(mx, v);
    }
    float sum = 0.0f;
    #pragma unroll
    for (int e = 0; e < En; e++) { lg[e] = expf(lg[e] - mx); sum += lg[e]; }
    float inv = 1.0f / sum;

    Outs O = make_outs(d_out, k);
    float pr[En];
    #pragma unroll
    for (int e = 0; e < En; e++) {
        pr[e] = (1.0f - eps) * (lg[e] * inv) + eps / (float)En;
        O.probs[b * En + e] = pr[e];
        O.mask[b * En + e]  = 0.0f;
    }

    // top-cand_k selection, ties -> lowest index first (strict >)
    bool used[En];
    #pragma unroll
    for (int e = 0; e < En; e++) used[e] = false;
    unsigned long long pk = 0ull;
    for (int j = 0; j < cand_k; j++) {
        float bv = -1e30f; int bi = 0;
        for (int e = 0; e < En; e++) {
            if (!used[e] && pr[e] > bv) { bv = pr[e]; bi = e; }
        }
        used[bi] = true;
        g_cand_val[b * CANDMAX + j] = bv;
        pk |= ((unsigned long long)bi) << (4 * j);
    }
    g_pack[b] = pk;

    for (int s = 0; s < k; s++) {
        g_assigned_idx[b * MAXK + s] = -1;
        g_assigned_w[b * MAXK + s]   = 0.0f;
        O.aidx[b * k + s] = -1.0f;
        O.aw[b * k + s]   = 0.0f;
        O.ev_e[s * Bn + b] = -1.0f;
        O.ev_a[s * Bn + b] = -1.0f;
    }
}

// =====================================================================
// Side work B: batched greedy capacity router. Single warp, 32 tok/iter.
// =====================================================================
__device__ void route_body(int lane,
                           const int* __restrict__ topk_p,
                           const int* __restrict__ cap_p,
                           float* __restrict__ d_out) {
    int k = *topk_p; if (k > En) k = En; if (k > MAXK) k = MAXK; if (k < 1) k = 1;
    int cand_k = 4 * k; if (cand_k < k) cand_k = k; if (cand_k > En) cand_k = En;
    int cap_lim = *cap_p; if (cap_lim < 1) cap_lim = 1;

    Outs O = make_outs(d_out, k);

    int cap = 0;            // lane < En holds cap[lane]
    unsigned closed = 0;
    int hits = 0;

    int t0 = 0;
    while (t0 < Bn) {
        const int t = t0 + lane;
        const bool has = (t < Bn);
        unsigned long long pk = has ? g_pack[t] : 0ull;

        unsigned take = 0;
        unsigned slotcand = 0;
        int nslots = 0;
        int myhits = 0;
        if (has) {
            for (int j = 0; j < cand_k; j++) {
                int e = (int)((pk >> (4 * j)) & 15ull);
                if (!((closed >> e) & 1u) && nslots < k) {
                    take |= (1u << e);
                    slotcand |= ((unsigned)j) << (4 * nslots);
                    if (j > 0) myhits++;
                    nslots++;
                }
            }
        }

        unsigned mybits = 0;
        #pragma unroll
        for (int e = 0; e < En; e++) {
            unsigned bb = __ballot_sync(0xffffffffu, (take >> e) & 1u);
            if (lane == e) mybits = bb;
        }
        int cnt = __popc(mybits);

        bool viol = (lane < En) && !((closed >> lane) & 1u) && (cap + cnt > cap_lim);
        unsigned vm = __ballot_sync(0xffffffffu, viol);
        int pstar = 32;
        if (vm) {
            int myp = 32;
            if (viol) {
                int rem = cap_lim - cap;
                unsigned m = mybits;
                for (int i = 0; i < rem; i++) m &= m - 1;
                myp = __ffs(m) - 1;
            }
            #pragma unroll
            for (int off = 16; off; off >>= 1) {
                int o = __shfl_xor_sync(0xffffffffu, myp, off);
                myp = min(myp, o);
            }
            pstar = myp;
        }

        unsigned commit_prefix = (pstar >= 32) ? 0xffffffffu : ((1u << pstar) - 1u);
        if (lane < En) cap += __popc(mybits & commit_prefix);

        if (has && lane < pstar) {
            for (int s = 0; s < nslots; s++) {
                int j = (int)((slotcand >> (4 * s)) & 15u);
                int e = (int)((pk >> (4 * j)) & 15ull);
                float v = g_cand_val[t * CANDMAX + j];
                g_assigned_idx[t * MAXK + s] = e;
                g_assigned_w[t * MAXK + s]   = v;
                O.aidx[t * k + s] = (float)e;
                O.aw[t * k + s]   = v;
                O.ev_e[s * Bn + t] = (float)e;
                O.mask[t * En + e] = 1.0f;
            }
            hits += myhits;
        }

        closed = __ballot_sync(0xffffffffu, (lane < En) && (cap >= cap_lim)) & 0xffffu;
        t0 += pstar;
    }

    #pragma unroll
    for (int off = 16; off; off >>= 1) hits += __shfl_xor_sync(0xffffffffu, hits, off);
    if (lane == 0) O.chr[0] = (float)hits / (float)(Bn * k);
}

// =====================================================================
// Fused BF16 GEMM + side work. 256 threads = 8 warps.
// GEMM (bx < NX): C[m,n] = act( sum_k A[m,k]*Wt[n,k] + bias[n] ),
//   block tile 128x64x32, warp tile 32x32 (4x2 warp grid), m16n8k16.bf16.
//   SMEM: bf16x2-packed uints, row pitch 20 uints (16 data + 4 pad):
//   fragment load bank = (20*g + tg + c) mod 32, all 32 lanes distinct.
//   Double-buffered, 30.7 KB total -> 2 blocks/SM.
// Side blocks (bx >= NX): SIDE=1 -> logits (8 warps = 8 tokens/block),
//                         SIDE=2 -> route (block (NX,0) warp 0 only).
// =====================================================================
#define TBM 128
#define TBN 64
#define TBK 32
#define PITCH 20                        // uints per row (k-dim 16 uints + pad)
#define GP ((TBM + TBN) * PITCH)        // uints per buffer

template <int ACT, int SIDE, int NX>
__global__ void __launch_bounds__(256, 2)
gemm_fused_kernel(const float* __restrict__ A, const float* __restrict__ Wt,
                  const float* __restrict__ bias, float* __restrict__ C,
                  int M, int N, int K,
                  const float* __restrict__ z, const float* __restrict__ proto,
                  const float* __restrict__ ebias,
                  const int* __restrict__ topk_p, const int* __restrict__ ban_p,
                  const float* __restrict__ tau_p, const float* __restrict__ eps_p,
                  const int* __restrict__ cap_p,
                  float* __restrict__ d_out) {
    const int bx = blockIdx.x;
    const int by = blockIdx.y;
    const int tid = threadIdx.x;
    const int warp = tid >> 5;   // 0..7
    const int lane = tid & 31;

    if (bx >= NX) {
        if (SIDE == 1) {
            int blk = (bx - NX) * gridDim.y + by;
            int b = blk * 8 + warp;
            if (b < Bn)
                logits_body(b, lane, z, proto, ebias, topk_p, ban_p, tau_p, eps_p, d_out);
        } else if (SIDE == 2) {
            if (by == 0 && warp == 0)
                route_body(lane, topk_p, cap_p, d_out);
        }
        return;
    }

    extern __shared__ unsigned smem_u[];

    const int g  = lane >> 2;   // 0..7
    const int tg = lane & 3;    // 0..3
    const int wq  = warp & 3;   // warp m index (0..3)
    const int wn2 = warp >> 2;  // warp n index (0..1)

    // staging: r0 = row 0..31, fq = float4 chunk 0..7 (k floats 4fq..4fq+3)
    const int r0 = tid >> 3;
    const int fq = tid & 7;

    const float* Aptr = A  + (size_t)(by * TBM) * K;
    const float* Bptr = Wt + (size_t)(bx * TBN) * K;

    float acc[2][4][4];
    #pragma unroll
    for (int i = 0; i < 2; i++)
        #pragma unroll
        for (int j = 0; j < 4; j++)
            #pragma unroll
            for (int c = 0; c < 4; c++) acc[i][j][c] = 0.0f;

    float4 ra[4], rb[2];
    #pragma unroll
    for (int i = 0; i < 4; i++)
        ra[i] = *(const float4*)(Aptr + (size_t)(r0 + 32 * i) * K + fq * 4);
    #pragma unroll
    for (int i = 0; i < 2; i++)
        rb[i] = *(const float4*)(Bptr + (size_t)(r0 + 32 * i) * K + fq * 4);

    // pack to bf16x2 and store; uint j of a row = k elements 2j, 2j+1
    auto stage_store = [&](int buf) {
        unsigned* As = smem_u + buf * GP;
        unsigned* Bs = As + TBM * PITCH;
        #pragma unroll
        for (int i = 0; i < 4; i++) {
            uint2 u;
            u.x = pack_bf16(ra[i].x, ra[i].y);
            u.y = pack_bf16(ra[i].z, ra[i].w);
            *(uint2*)(&As[(r0 + 32 * i) * PITCH + fq * 2]) = u;
        }
        #pragma unroll
        for (int i = 0; i < 2; i++) {
            uint2 u;
            u.x = pack_bf16(rb[i].x, rb[i].y);
            u.y = pack_bf16(rb[i].z, rb[i].w);
            *(uint2*)(&Bs[(r0 + 32 * i) * PITCH + fq * 2]) = u;
        }
    };

    stage_store(0);
    __syncthreads();

    const int KIT = K / TBK;
    for (int kt = 0; kt < KIT; kt++) {
        const int cur = kt & 1;
        const bool more = (kt + 1 < KIT);
        const unsigned* AsC = smem_u + cur * GP;
        const unsigned* BsC = AsC + TBM * PITCH;

        if (more) {
            int k0 = (kt + 1) * TBK;
            #pragma unroll
            for (int i = 0; i < 4; i++)
                ra[i] = *(const float4*)(Aptr + (size_t)(r0 + 32 * i) * K + k0 + fq * 4);
            #pragma unroll
            for (int i = 0; i < 2; i++)
                rb[i] = *(const float4*)(Bptr + (size_t)(r0 + 32 * i) * K + k0 + fq * 4);
        }

        // 2 k16 steps per TBK=32
        #pragma unroll
        for (int kk = 0; kk < 2; kk++) {
            unsigned afr[2][4];
            #pragma unroll
            for (int mi = 0; mi < 2; mi++) {
                int row = wq * 32 + mi * 16 + g;
                afr[mi][0] = AsC[row * PITCH + kk * 8 + tg];
                afr[mi][1] = AsC[(row + 8) * PITCH + kk * 8 + tg];
                afr[mi][2] = AsC[row * PITCH + kk * 8 + tg + 4];
                afr[mi][3] = AsC[(row + 8) * PITCH + kk * 8 + tg + 4];
            }
            unsigned bfr[4][2];
            #pragma unroll
            for (int ni = 0; ni < 4; ni++) {
                int col = wn2 * 32 + ni * 8 + g;
                bfr[ni][0] = BsC[col * PITCH + kk * 8 + tg];
                bfr[ni][1] = BsC[col * PITCH + kk * 8 + tg + 4];
            }
            #pragma unroll
            for (int mi = 0; mi < 2; mi++)
                #pragma unroll
                for (int ni = 0; ni < 4; ni++)
                    mma_bf16(acc[mi][ni], afr[mi], bfr[ni]);
        }

        if (more) stage_store(1 - cur);
        __syncthreads();
    }

    // epilogue: thread (g,tg) owns rows g,g+8 cols 2tg,2tg+1 of each 16x8 tile
    #pragma unroll
    for (int mi = 0; mi < 2; mi++) {
        int row0 = by * TBM + wq * 32 + mi * 16 + g;
        #pragma unroll
        for (int ni = 0; ni < 4; ni++) {
            int col = bx * TBN + wn2 * 32 + ni * 8 + 2 * tg;
            float b0 = bias[col], b1 = bias[col + 1];
            float v0 = acc[mi][ni][0] + b0;
            float v1 = acc[mi][ni][1] + b1;
            float v2 = acc[mi][ni][2] + b0;
            float v3 = acc[mi][ni][3] + b1;
            if (ACT) { v0 = silu_f(v0); v1 = silu_f(v1); v2 = silu_f(v2); v3 = silu_f(v3); }
            *(float2*)(&C[(size_t)row0 * N + col])       = make_float2(v0, v1);
            *(float2*)(&C[(size_t)(row0 + 8) * N + col]) = make_float2(v2, v3);
        }
    }
}

// =====================================================================
// Adapter selection + LoRA apply + final output (round-3 version).
// =====================================================================
__global__ void __launch_bounds__(256)
adapter_kernel(const float* __restrict__ z,
               const float* __restrict__ ak,
               const float* __restrict__ a1, const float* __restrict__ b1,
               const float* __restrict__ a2, const float* __restrict__ b2,
               const int* __restrict__ topk_p,
               float* __restrict__ d_out) {
    __shared__ float s_z[Dn];
    __shared__ float s_hp[Hn];
    __shared__ float s_h[2][Hn];
    __shared__ float s_t1[2][Rn];
    __shared__ float s_t2[2][Rn];
    __shared__ float s_sc[2][Wn];
    __shared__ int   s_base[2];
    __shared__ float s_wgt[2];
    __shared__ int   s_valid[2];

    const int b = blockIdx.x;
    const int tid = threadIdx.x;
    const int lane = tid & 31;
    const int warp = tid >> 5;
    const int group = warp >> 2;
    const int wig = warp & 3;
    const int gt = tid & 127;

    int k = *topk_p; if (k > En) k = En; if (k > MAXK) k = MAXK; if (k < 1) k = 1;
    Outs O = make_outs(d_out, k);

    for (int i = tid; i < Dn; i += 256) s_z[i] = z[(size_t)b * Dn + i];
    for (int i = tid; i < Hn; i += 256) s_hp[i] = g_hpre[(size_t)b * Hn + i];

    float opre[Dn / 256];
    float accd[Dn / 256];
    #pragma unroll
    for (int i = 0; i < Dn / 256; i++) {
        opre[i] = g_outpre[(size_t)b * Dn + tid + i * 256];
        accd[i] = 0.0f;
    }
    __syncthreads();

    for (int s0 = 0; s0 < k; s0 += 2) {
        const int sA = s0 + group;
        const bool act = (sA < k);
        int e = -1;
        float wgt = 0.0f;
        if (act) {
            e   = g_assigned_idx[b * MAXK + sA];
            wgt = g_assigned_w[b * MAXK + sA];
        }
        const bool valid = act && (e >= 0);

        if (valid) {
            const float* akr = ak + (size_t)(e * Wn + wig) * Dn;
            float p0 = 0.0f, p1 = 0.0f;
            for (int d = lane; d < Dn; d += 64) {
                p0 += s_z[d] * akr[d];
                p1 += s_z[d + 32] * akr[d + 32];
            }
            float p = warp_reduce(p0 + p1);
            if (lane == 0) s_sc[group][wig] = p;
        }
        __syncthreads();

        if (gt == 0) {
            if (valid) {
                float bv = s_sc[group][0]; int bi = 0;
                #pragma unroll
                for (int w2 = 1; w2 < Wn; w2++)
                    if (s_sc[group][w2] > bv) { bv = s_sc[group][w2]; bi = w2; }
                s_base[group] = e * Wn + bi;
                s_wgt[group] = wgt;
                s_valid[group] = 1;
                O.ev_a[sA * Bn + b] = (float)bi;
            } else {
                s_valid[group] = 0;
            }
        }
        __syncthreads();

        const int base = s_base[group];

        if (valid) {
            const float* A1r0 = a1 + ((size_t)base * Rn + 2 * wig) * Dn;
            const float* A1r1 = A1r0 + Dn;
            float q0 = 0.0f, q1 = 0.0f;
            for (int d = lane; d < Dn; d += 32) {
                float zv = s_z[d];
                q0 += zv * A1r0[d];
                q1 += zv * A1r1[d];
            }
            q0 = warp_reduce(q0);
            q1 = warp_reduce(q1);
            if (lane == 0) { s_t1[group][2 * wig] = q0; s_t1[group][2 * wig + 1] = q1; }
        }
        __syncthreads();

        if (valid) {
            float t1r[Rn];
            #pragma unroll
            for (int r = 0; r < Rn; r++) t1r[r] = s_t1[group][r];
            for (int h = gt; h < Hn; h += 128) {
                const float* B1r = b1 + ((size_t)base * Hn + h) * Rn;
                float d1 = 0.0f;
                #pragma unroll
                for (int r = 0; r < Rn; r++) d1 += t1r[r] * B1r[r];
                s_h[group][h] = silu_f(s_hp[h] + d1 * SCALE_C);
            }
        }
        __syncthreads();

        if (valid) {
            const float* A2r0 = a2 + ((size_t)base * Rn + 2 * wig) * Hn;
            const float* A2r1 = A2r0 + Hn;
            float q0 = 0.0f, q1 = 0.0f;
            for (int h2 = lane; h2 < Hn; h2 += 32) {
                float hv = s_h[group][h2];
                q0 += hv * A2r0[h2];
                q1 += hv * A2r1[h2];
            }
            q0 = warp_reduce(q0);
            q1 = warp_reduce(q1);
            if (lane == 0) { s_t2[group][2 * wig] = q0; s_t2[group][2 * wig + 1] = q1; }
        }
        __syncthreads();

        #pragma unroll
        for (int gg = 0; gg < 2; gg++) {
            if (s_valid[gg]) {
                const int bs = s_base[gg];
                const float wg = s_wgt[gg];
                float t2r[Rn];
                #pragma unroll
                for (int r = 0; r < Rn; r++) t2r[r] = s_t2[gg][r];
                #pragma unroll
                for (int i = 0; i < Dn / 256; i++) {
                    int d = tid + i * 256;
                    const float* B2r = b2 + ((size_t)bs * Dn + d) * Rn;
                    float d2 = 0.0f;
                    #pragma unroll
                    for (int r = 0; r < Rn; r++) d2 += t2r[r] * B2r[r];
                    accd[i] += wg * (opre[i] + d2 * SCALE_C);
                }
            }
        }
        __syncthreads();
    }

    #pragma unroll
    for (int i = 0; i < Dn / 256; i++) {
        int d = tid + i * 256;
        O.z[(size_t)b * Dn + d] = s_z[d] + accd[i];
    }
}

// =====================================================================
// launch
// =====================================================================
extern "C" void kernel_launch(void* const* d_in, const int* in_sizes, int n_in,
                              void* d_out, int out_size) {
    const float* z     = (const float*)d_in[0];
    const int*   topk  = (const int*)  d_in[1];
    const int*   cap   = (const int*)  d_in[2];
    const int*   ban   = (const int*)  d_in[3];
    const float* tau   = (const float*)d_in[4];
    const float* eps   = (const float*)d_in[5];
    const float* fc1w  = (const float*)d_in[6];
    const float* fc1b  = (const float*)d_in[7];
    const float* fc2w  = (const float*)d_in[8];
    const float* fc2b  = (const float*)d_in[9];
    const float* proto = (const float*)d_in[10];
    const float* ak    = (const float*)d_in[11];
    const float* ebias = (const float*)d_in[12];
    const float* a1    = (const float*)d_in[13];
    const float* b1    = (const float*)d_in[14];
    const float* a2    = (const float*)d_in[15];
    const float* b2    = (const float*)d_in[16];
    float* out = (float*)d_out;

    float *hpre_ptr = nullptr, *outpre_ptr = nullptr;
    cudaGetSymbolAddress((void**)&hpre_ptr, g_hpre);
    cudaGetSymbolAddress((void**)&outpre_ptr, g_outpre);

    const int gemm_smem = 2 * GP * sizeof(unsigned);  // 30720
    cudaFuncSetAttribute((const void*)gemm_fused_kernel<1, 1, 32>,
                         cudaFuncAttributeMaxDynamicSharedMemorySize, gemm_smem);
    cudaFuncSetAttribute((const void*)gemm_fused_kernel<0, 2, 16>,
                         cudaFuncAttributeMaxDynamicSharedMemorySize, gemm_smem);

    // 1) h_pre = silu(z @ fc1_w^T + fc1_b)  [B,H] + logits/topk side blocks
    //    grid: 32 gemm n-cols (2048/64) x 16 m-rows, + 16 side cols
    //    (256 side blocks x 8 warps = 2048 tokens)
    gemm_fused_kernel<1, 1, 32><<<dim3(48, 16), 256, gemm_smem>>>(
        z, fc1w, fc1b, hpre_ptr, Bn, Hn, Dn,
        z, proto, ebias, topk, ban, tau, eps, cap, out);

    // 2) out_pre = h_pre @ fc2_w^T + fc2_b  [B,D] + router side block
    //    grid: 16 gemm n-cols (1024/64) x 16 m-rows, + 1 side col
    gemm_fused_kernel<0, 2, 16><<<dim3(17, 16), 256, gemm_smem>>>(
        hpre_ptr, fc2w, fc2b, outpre_ptr, Bn, Dn, Hn,
        z, proto, ebias, topk, ban, tau, eps, cap, out);

    // 3) adapter select + LoRA deltas + final combine
    adapter_kernel<<<Bn, 256>>>(z, ak, a1, b1, a2, b2, topk, out);
}

// round 8
// speedup vs baseline: 1.8843x; 1.2065x over previous
#include <cuda_runtime.h>
#include <math.h>

// Problem constants (fixed by the dataset)
#define Bn 2048
#define Dn 1024
#define Hn 2048
#define En 16
#define Wn 4
#define Rn 8
#define MAXK 4
#define CANDMAX 16
#define SCALE_C 1.0f

// ---------------- scratch (device globals; no allocation allowed) -----------
__device__ float g_hpre[Bn * Hn];     // fp32 hpre (adapter)
__device__ float g_outpre[Bn * Dn];
__device__ float g_cand_val[Bn * CANDMAX];
__device__ unsigned long long g_pack[Bn];
__device__ int   g_assigned_idx[Bn * MAXK];
__device__ float g_assigned_w[Bn * MAXK];
// bf16 (pair-packed) copies
__device__ unsigned g_z_bf[Bn * Dn / 2];
__device__ unsigned g_w1_bf[Hn * Dn / 2];
__device__ unsigned g_w2_bf[Dn * Hn / 2];
__device__ unsigned g_hpre_bf[Bn * Hn / 2];
__device__ unsigned g_a1_bf[En * Wn * Rn * Dn / 2];
__device__ unsigned g_b1_bf[En * Wn * Hn * Rn / 2];
__device__ unsigned g_a2_bf[En * Wn * Rn * Hn / 2];
__device__ unsigned g_b2_bf[En * Wn * Dn * Rn / 2];

// ---------------- output layout ----------------
struct Outs {
    float *z, *probs, *mask, *aidx, *aw, *chr, *ev_e, *ev_a;
};
__host__ __device__ __forceinline__ Outs make_outs(float* o, int k) {
    Outs s;
    s.z     = o; o += Bn * Dn;
    s.probs = o; o += Bn * En;
    s.mask  = o; o += Bn * En;
    s.aidx  = o; o += Bn * k;
    s.aw    = o; o += Bn * k;
    s.chr   = o; o += 1;
    s.ev_e  = o; o += (size_t)k * Bn;
    s.ev_a  = o;
    return s;
}

__device__ __forceinline__ float warp_reduce(float v) {
    #pragma unroll
    for (int off = 16; off; off >>= 1) v += __shfl_xor_sync(0xffffffffu, v, off);
    return v;
}
__device__ __forceinline__ float silu_f(float x) { return x / (1.0f + expf(-x)); }

__device__ __forceinline__ unsigned pack_bf16(float lo, float hi) {
    unsigned r;
    asm("cvt.rn.bf16x2.f32 %0, %1, %2;" : "=r"(r) : "f"(hi), "f"(lo));
    return r;
}
__device__ __forceinline__ float bf_lo(unsigned u) { return __uint_as_float(u << 16); }
__device__ __forceinline__ float bf_hi(unsigned u) { return __uint_as_float(u & 0xffff0000u); }

__device__ __forceinline__ void mma_bf16(float* d, const unsigned* a, const unsigned* b) {
    asm volatile(
        "mma.sync.aligned.m16n8k16.row.col.f32.bf16.bf16.f32 "
        "{%0,%1,%2,%3}, {%4,%5,%6,%7}, {%8,%9}, {%0,%1,%2,%3};"
        : "+f"(d[0]), "+f"(d[1]), "+f"(d[2]), "+f"(d[3])
        : "r"(a[0]), "r"(a[1]), "r"(a[2]), "r"(a[3]), "r"(b[0]), "r"(b[1]));
}

__device__ __forceinline__ void cp_async16(unsigned* smem_dst, const void* gmem_src) {
    unsigned saddr = (unsigned)__cvta_generic_to_shared(smem_dst);
    asm volatile("cp.async.cg.shared.global [%0], [%1], 16;" :: "r"(saddr), "l"(gmem_src));
}
#define CP_COMMIT() asm volatile("cp.async.commit_group;")
#define CP_WAIT2()  asm volatile("cp.async.wait_group 2;")

// =====================================================================
// Convert kernel: fp32 -> bf16x2-packed copies of z, fc1_w, fc2_w,
// a1, b1, a2, b2. One-time, elementwise (layouts preserved).
// =====================================================================
#define CV0 (Bn * Dn / 2)
#define CV1 (CV0 + Hn * Dn / 2)
#define CV2 (CV1 + Dn * Hn / 2)
#define CV3 (CV2 + En * Wn * Rn * Dn / 2)
#define CV4 (CV3 + En * Wn * Hn * Rn / 2)
#define CV5 (CV4 + En * Wn * Rn * Hn / 2)
#define CV6 (CV5 + En * Wn * Dn * Rn / 2)

__global__ void __launch_bounds__(256)
convert_kernel(const float* __restrict__ z,  const float* __restrict__ w1,
               const float* __restrict__ w2, const float* __restrict__ a1,
               const float* __restrict__ b1, const float* __restrict__ a2,
               const float* __restrict__ b2) {
    for (int idx = blockIdx.x * 256 + threadIdx.x; idx < CV6; idx += gridDim.x * 256) {
        const float2* s; unsigned* d; int off;
        if      (idx < CV0) { s = (const float2*)z;  d = g_z_bf;  off = idx; }
        else if (idx < CV1) { s = (const float2*)w1; d = g_w1_bf; off = idx - CV0; }
        else if (idx < CV2) { s = (const float2*)w2; d = g_w2_bf; off = idx - CV1; }
        else if (idx < CV3) { s = (const float2*)a1; d = g_a1_bf; off = idx - CV2; }
        else if (idx < CV4) { s = (const float2*)b1; d = g_b1_bf; off = idx - CV3; }
        else if (idx < CV5) { s = (const float2*)a2; d = g_a2_bf; off = idx - CV4; }
        else                { s = (const float2*)b2; d = g_b2_bf; off = idx - CV5; }
        float2 v = s[off];
        d[off] = pack_bf16(v.x, v.y);
    }
}

// =====================================================================
// Side work A: logits/softmax/top-cand (fp32, one warp per token).
// =====================================================================
__device__ void logits_body(int b, int lane,
                            const float* __restrict__ z,
                            const float* __restrict__ proto,
                            const float* __restrict__ ebias,
                            const int* __restrict__ topk_p,
                            const int* __restrict__ ban_p,
                            const float* __restrict__ tau_p,
                            const float* __restrict__ eps_p,
                            float* __restrict__ d_out) {
    const float* zr = z + (size_t)b * Dn;

    float acc[En];
    #pragma unroll
    for (int e = 0; e < En; e++) acc[e] = 0.0f;
    for (int d = lane; d < Dn; d += 32) {
        float zv = zr[d];
        #pragma unroll
        for (int e = 0; e < En; e++) acc[e] += zv * proto[e * Dn + d];
    }
    #pragma unroll
    for (int e = 0; e < En; e++) acc[e] = warp_reduce(acc[e]);

    if (lane != 0) return;

    int k = *topk_p; if (k > En) k = En; if (k > MAXK) k = MAXK; if (k < 1) k = 1;
    int cand_k = 4 * k; if (cand_k < k) cand_k = k; if (cand_k > En) cand_k = En;
    int ban = *ban_p;
    float inv_tau = 1.0f / fmaxf(*tau_p, 1e-6f);
    float eps = *eps_p;

    float lg[En];
    float mx = -1e30f;
    #pragma unroll
    for (int e = 0; e < En; e++) {
        float v = acc[e] * inv_tau + ebias[e];
        if (e == ban) v = -1e9f;
        lg[e] = v;
        mx = fmaxf(mx, v);
    }
    float sum = 0.0f;
    #pragma unroll
    for (int e = 0; e < En; e++) { lg[e] = expf(lg[e] - mx); sum += lg[e]; }
    float inv = 1.0f / sum;

    Outs O = make_outs(d_out, k);
    float pr[En];
    #pragma unroll
    for (int e = 0; e < En; e++) {
        pr[e] = (1.0f - eps) * (lg[e] * inv) + eps / (float)En;
        O.probs[b * En + e] = pr[e];
        O.mask[b * En + e]  = 0.0f;
    }

    bool used[En];
    #pragma unroll
    for (int e = 0; e < En; e++) used[e] = false;
    unsigned long long pk = 0ull;
    for (int j = 0; j < cand_k; j++) {
        float bv = -1e30f; int bi = 0;
        for (int e = 0; e < En; e++)
            if (!used[e] && pr[e] > bv) { bv = pr[e]; bi = e; }
        used[bi] = true;
        g_cand_val[b * CANDMAX + j] = bv;
        pk |= ((unsigned long long)bi) << (4 * j);
    }
    g_pack[b] = pk;

    for (int s = 0; s < k; s++) {
        g_assigned_idx[b * MAXK + s] = -1;
        g_assigned_w[b * MAXK + s]   = 0.0f;
        O.aidx[b * k + s] = -1.0f;
        O.aw[b * k + s]   = 0.0f;
        O.ev_e[s * Bn + b] = -1.0f;
        O.ev_a[s * Bn + b] = -1.0f;
    }
}

// =====================================================================
// Side work B: batched greedy capacity router (single warp).
// =====================================================================
__device__ void route_body(int lane,
                           const int* __restrict__ topk_p,
                           const int* __restrict__ cap_p,
                           float* __restrict__ d_out) {
    int k = *topk_p; if (k > En) k = En; if (k > MAXK) k = MAXK; if (k < 1) k = 1;
    int cand_k = 4 * k; if (cand_k < k) cand_k = k; if (cand_k > En) cand_k = En;
    int cap_lim = *cap_p; if (cap_lim < 1) cap_lim = 1;

    Outs O = make_outs(d_out, k);

    int cap = 0;
    unsigned closed = 0;
    int hits = 0;

    int t0 = 0;
    while (t0 < Bn) {
        const int t = t0 + lane;
        const bool has = (t < Bn);
        unsigned long long pk = has ? g_pack[t] : 0ull;

        unsigned take = 0, slotcand = 0;
        int nslots = 0, myhits = 0;
        if (has) {
            for (int j = 0; j < cand_k; j++) {
                int e = (int)((pk >> (4 * j)) & 15ull);
                if (!((closed >> e) & 1u) && nslots < k) {
                    take |= (1u << e);
                    slotcand |= ((unsigned)j) << (4 * nslots);
                    if (j > 0) myhits++;
                    nslots++;
                }
            }
        }

        unsigned mybits = 0;
        #pragma unroll
        for (int e = 0; e < En; e++) {
            unsigned bb = __ballot_sync(0xffffffffu, (take >> e) & 1u);
            if (lane == e) mybits = bb;
        }
        int cnt = __popc(mybits);

        bool viol = (lane < En) && !((closed >> lane) & 1u) && (cap + cnt > cap_lim);
        unsigned vm = __ballot_sync(0xffffffffu, viol);
        int pstar = 32;
        if (vm) {
            int myp = 32;
            if (viol) {
                int rem = cap_lim - cap;
                unsigned m = mybits;
                for (int i = 0; i < rem; i++) m &= m - 1;
                myp = __ffs(m) - 1;
            }
            #pragma unroll
            for (int off = 16; off; off >>= 1) {
                int o = __shfl_xor_sync(0xffffffffu, myp, off);
                myp = min(myp, o);
            }
            pstar = myp;
        }

        unsigned commit_prefix = (pstar >= 32) ? 0xffffffffu : ((1u << pstar) - 1u);
        if (lane < En) cap += __popc(mybits & commit_prefix);

        if (has && lane < pstar) {
            for (int s = 0; s < nslots; s++) {
                int j = (int)((slotcand >> (4 * s)) & 15u);
                int e = (int)((pk >> (4 * j)) & 15ull);
                float v = g_cand_val[t * CANDMAX + j];
                g_assigned_idx[t * MAXK + s] = e;
                g_assigned_w[t * MAXK + s]   = v;
                O.aidx[t * k + s] = (float)e;
                O.aw[t * k + s]   = v;
                O.ev_e[s * Bn + t] = (float)e;
                O.mask[t * En + e] = 1.0f;
            }
            hits += myhits;
        }

        closed = __ballot_sync(0xffffffffu, (lane < En) && (cap >= cap_lim)) & 0xffffu;
        t0 += pstar;
    }

    #pragma unroll
    for (int off = 16; off; off >>= 1) hits += __shfl_xor_sync(0xffffffffu, hits, off);
    if (lane == 0) O.chr[0] = (float)hits / (float)(Bn * k);
}

// =====================================================================
// Fused BF16 GEMM (cp.async 4-stage pipeline) + side work.
// GEMM (bx < NX): C[m,n] = act( sum_k A[m,k]*Wt[n,k] + bias[n] ),
//   A, Wt are bf16 row-major [., K]. Block tile 128x64x32, 8 warps,
//   warp tile 32x32, m16n8k16. SMEM pitch 20 uints/row (same bank map
//   as round 7, proven conflict-free). 4 stages x 15,360B = 61,440B.
//   cp.async.cg 16B chunks: 192 rows x 4 chunks = 768 = 3/thread.
// ACT==1 also writes bf16 copy of C (feeds next GEMM).
// =====================================================================
#define TBM 128
#define TBN 64
#define TBK 32
#define PITCH 20
#define STG ((TBM + TBN) * PITCH)   // uints per stage
#define NSTAGE 4

template <int ACT, int SIDE, int NX>
__global__ void __launch_bounds__(256, 2)
gemm_fused_kernel(const unsigned short* __restrict__ Abf,
                  const unsigned short* __restrict__ Wbf,
                  const float* __restrict__ bias, float* __restrict__ C,
                  unsigned* __restrict__ Cbf,
                  int M, int N, int K,
                  const float* __restrict__ z, const float* __restrict__ proto,
                  const float* __restrict__ ebias,
                  const int* __restrict__ topk_p, const int* __restrict__ ban_p,
                  const float* __restrict__ tau_p, const float* __restrict__ eps_p,
                  const int* __restrict__ cap_p,
                  float* __restrict__ d_out) {
    const int bx = blockIdx.x;
    const int by = blockIdx.y;
    const int tid = threadIdx.x;
    const int warp = tid >> 5;
    const int lane = tid & 31;

    if (bx >= NX) {
        if (SIDE == 1) {
            int blk = (bx - NX) * gridDim.y + by;
            int b = blk * 8 + warp;
            if (b < Bn)
                logits_body(b, lane, z, proto, ebias, topk_p, ban_p, tau_p, eps_p, d_out);
        } else if (SIDE == 2) {
            if (by == 0 && warp == 0)
                route_body(lane, topk_p, cap_p, d_out);
        }
        return;
    }

    extern __shared__ unsigned smem_u[];

    const int g  = lane >> 2;
    const int tg = lane & 3;
    const int wq  = warp & 3;
    const int wn2 = warp >> 5 == 0 ? (warp >> 2) : 0;  // warp>>2 (0..1)

    float acc[2][4][4];
    #pragma unroll
    for (int i = 0; i < 2; i++)
        #pragma unroll
        for (int j = 0; j < 4; j++)
            #pragma unroll
            for (int c = 0; c < 4; c++) acc[i][j][c] = 0.0f;

    // cp.async staging: 3 chunks per thread
    auto issue = [&](int buf, int kt) {
        unsigned* base = smem_u + buf * STG;
        const int k0 = kt * TBK;
        #pragma unroll
        for (int i = 0; i < 3; i++) {
            int c = tid + i * 256;
            int row = c >> 2, ch = c & 3;
            const unsigned short* src;
            if (row < TBM) src = Abf + (size_t)(by * TBM + row) * K + k0 + ch * 8;
            else           src = Wbf + (size_t)(bx * TBN + row - TBM) * K + k0 + ch * 8;
            cp_async16(base + row * PITCH + ch * 4, (const void*)src);
        }
    };

    const int KIT = K / TBK;
    #pragma unroll
    for (int s = 0; s < NSTAGE - 1; s++) {
        if (s < KIT) issue(s, s);
        CP_COMMIT();
    }

    for (int kt = 0; kt < KIT; kt++) {
        CP_WAIT2();
        __syncthreads();
        if (kt + NSTAGE - 1 < KIT) issue((kt + NSTAGE - 1) & 3, kt + NSTAGE - 1);
        CP_COMMIT();

        const unsigned* AsC = smem_u + (kt & 3) * STG;
        const unsigned* BsC = AsC + TBM * PITCH;

        #pragma unroll
        for (int kk = 0; kk < 2; kk++) {
            unsigned afr[2][4];
            #pragma unroll
            for (int mi = 0; mi < 2; mi++) {
                int row = wq * 32 + mi * 16 + g;
                afr[mi][0] = AsC[row * PITCH + kk * 8 + tg];
                afr[mi][1] = AsC[(row + 8) * PITCH + kk * 8 + tg];
                afr[mi][2] = AsC[row * PITCH + kk * 8 + tg + 4];
                afr[mi][3] = AsC[(row + 8) * PITCH + kk * 8 + tg + 4];
            }
            unsigned bfr[4][2];
            #pragma unroll
            for (int ni = 0; ni < 4; ni++) {
                int col = wn2 * 32 + ni * 8 + g;
                bfr[ni][0] = BsC[col * PITCH + kk * 8 + tg];
                bfr[ni][1] = BsC[col * PITCH + kk * 8 + tg + 4];
            }
            #pragma unroll
            for (int mi = 0; mi < 2; mi++)
                #pragma unroll
                for (int ni = 0; ni < 4; ni++)
                    mma_bf16(acc[mi][ni], afr[mi], bfr[ni]);
        }
    }

    // epilogue
    #pragma unroll
    for (int mi = 0; mi < 2; mi++) {
        int row0 = by * TBM + wq * 32 + mi * 16 + g;
        #pragma unroll
        for (int ni = 0; ni < 4; ni++) {
            int col = bx * TBN + wn2 * 32 + ni * 8 + 2 * tg;
            float b0 = bias[col], b1 = bias[col + 1];
            float v0 = acc[mi][ni][0] + b0;
            float v1 = acc[mi][ni][1] + b1;
            float v2 = acc[mi][ni][2] + b0;
            float v3 = acc[mi][ni][3] + b1;
            if (ACT) { v0 = silu_f(v0); v1 = silu_f(v1); v2 = silu_f(v2); v3 = silu_f(v3); }
            *(float2*)(&C[(size_t)row0 * N + col])       = make_float2(v0, v1);
            *(float2*)(&C[(size_t)(row0 + 8) * N + col]) = make_float2(v2, v3);
            if (ACT) {
                Cbf[((size_t)row0 * N + col) >> 1]       = pack_bf16(v0, v1);
                Cbf[((size_t)(row0 + 8) * N + col) >> 1] = pack_bf16(v2, v3);
            }
        }
    }
}

// =====================================================================
// Adapter selection + LoRA apply + final output. One block per token;
// two slots concurrently by two 4-warp groups. LoRA weights read as
// bf16 (half traffic), math in fp32; adapter_keys stay fp32 (argmax).
// =====================================================================
__global__ void __launch_bounds__(256)
adapter_kernel(const float* __restrict__ z,
               const float* __restrict__ ak,
               const unsigned* __restrict__ a1b, const unsigned* __restrict__ b1b,
               const unsigned* __restrict__ a2b, const unsigned* __restrict__ b2b,
               const int* __restrict__ topk_p,
               float* __restrict__ d_out) {
    __shared__ float s_z[Dn];
    __shared__ float s_hp[Hn];
    __shared__ float s_h[2][Hn];
    __shared__ float s_t1[2][Rn];
    __shared__ float s_t2[2][Rn];
    __shared__ float s_sc[2][Wn];
    __shared__ int   s_base[2];
    __shared__ float s_wgt[2];
    __shared__ int   s_valid[2];

    const int b = blockIdx.x;
    const int tid = threadIdx.x;
    const int lane = tid & 31;
    const int warp = tid >> 5;
    const int group = warp >> 2;
    const int wig = warp & 3;
    const int gt = tid & 127;

    int k = *topk_p; if (k > En) k = En; if (k > MAXK) k = MAXK; if (k < 1) k = 1;
    Outs O = make_outs(d_out, k);

    for (int i = tid; i < Dn; i += 256) s_z[i] = z[(size_t)b * Dn + i];
    for (int i = tid; i < Hn; i += 256) s_hp[i] = g_hpre[(size_t)b * Hn + i];

    float opre[Dn / 256];
    float accd[Dn / 256];
    #pragma unroll
    for (int i = 0; i < Dn / 256; i++) {
        opre[i] = g_outpre[(size_t)b * Dn + tid + i * 256];
        accd[i] = 0.0f;
    }
    __syncthreads();

    for (int s0 = 0; s0 < k; s0 += 2) {
        const int sA = s0 + group;
        const bool act = (sA < k);
        int e = -1;
        float wgt = 0.0f;
        if (act) {
            e   = g_assigned_idx[b * MAXK + sA];
            wgt = g_assigned_w[b * MAXK + sA];
        }
        const bool valid = act && (e >= 0);

        // phase 1: adapter-key dots (fp32)
        if (valid) {
            const float* akr = ak + (size_t)(e * Wn + wig) * Dn;
            float p0 = 0.0f, p1 = 0.0f;
            for (int d = lane; d < Dn; d += 64) {
                p0 += s_z[d] * akr[d];
                p1 += s_z[d + 32] * akr[d + 32];
            }
            float p = warp_reduce(p0 + p1);
            if (lane == 0) s_sc[group][wig] = p;
        }
        __syncthreads();

        if (gt == 0) {
            if (valid) {
                float bv = s_sc[group][0]; int bi = 0;
                #pragma unroll
                for (int w2 = 1; w2 < Wn; w2++)
                    if (s_sc[group][w2] > bv) { bv = s_sc[group][w2]; bi = w2; }
                s_base[group] = e * Wn + bi;
                s_wgt[group] = wgt;
                s_valid[group] = 1;
                O.ev_a[sA * Bn + b] = (float)bi;
            } else {
                s_valid[group] = 0;
            }
        }
        __syncthreads();

        const int base = s_base[group];

        // phase 3: t1[r] = z . A1[base, r, :]  (bf16 weights)
        if (valid) {
            const uint2* A1r0 = (const uint2*)a1b + ((size_t)base * Rn + 2 * wig) * (Dn / 4);
            const uint2* A1r1 = A1r0 + (Dn / 4);
            float q0 = 0.0f, q1 = 0.0f;
            #pragma unroll
            for (int i = 0; i < Dn / 128; i++) {
                int idx = lane + i * 32;
                float4 zz = *(const float4*)&s_z[idx * 4];
                uint2 u0 = A1r0[idx], u1 = A1r1[idx];
                q0 += zz.x * bf_lo(u0.x) + zz.y * bf_hi(u0.x)
                    + zz.z * bf_lo(u0.y) + zz.w * bf_hi(u0.y);
                q1 += zz.x * bf_lo(u1.x) + zz.y * bf_hi(u1.x)
                    + zz.z * bf_lo(u1.y) + zz.w * bf_hi(u1.y);
            }
            q0 = warp_reduce(q0);
            q1 = warp_reduce(q1);
            if (lane == 0) { s_t1[group][2 * wig] = q0; s_t1[group][2 * wig + 1] = q1; }
        }
        __syncthreads();

        // phase 4: h = silu(h_pre + t1 . B1)   (B1 row = one uint4)
        if (valid) {
            float t1r[Rn];
            #pragma unroll
            for (int r = 0; r < Rn; r++) t1r[r] = s_t1[group][r];
            const uint4* B1q = (const uint4*)b1b + (size_t)base * Hn;
            for (int h = gt; h < Hn; h += 128) {
                uint4 q = B1q[h];
                float d1 = t1r[0] * bf_lo(q.x) + t1r[1] * bf_hi(q.x)
                         + t1r[2] * bf_lo(q.y) + t1r[3] * bf_hi(q.y)
                         + t1r[4] * bf_lo(q.z) + t1r[5] * bf_hi(q.z)
                         + t1r[6] * bf_lo(q.w) + t1r[7] * bf_hi(q.w);
                s_h[group][h] = silu_f(s_hp[h] + d1 * SCALE_C);
            }
        }
        __syncthreads();

        // phase 5: t2[r] = h . A2[base, r, :]
        if (valid) {
            const uint2* A2r0 = (const uint2*)a2b + ((size_t)base * Rn + 2 * wig) * (Hn / 4);
            const uint2* A2r1 = A2r0 + (Hn / 4);
            float q0 = 0.0f, q1 = 0.0f;
            #pragma unroll
            for (int i = 0; i < Hn / 128; i++) {
                int idx = lane + i * 32;
                float4 hh = *(const float4*)&s_h[group][idx * 4];
                uint2 u0 = A2r0[idx], u1 = A2r1[idx];
                q0 += hh.x * bf_lo(u0.x) + hh.y * bf_hi(u0.x)
                    + hh.z * bf_lo(u0.y) + hh.w * bf_hi(u0.y);
                q1 += hh.x * bf_lo(u1.x) + hh.y * bf_hi(u1.x)
                    + hh.z * bf_lo(u1.y) + hh.w * bf_hi(u1.y);
            }
            q0 = warp_reduce(q0);
            q1 = warp_reduce(q1);
            if (lane == 0) { s_t2[group][2 * wig] = q0; s_t2[group][2 * wig + 1] = q1; }
        }
        __syncthreads();

        // phase 6: accumulate both groups' deltas (B2 row = one uint4)
        #pragma unroll
        for (int gg = 0; gg < 2; gg++) {
            if (s_valid[gg]) {
                const int bs = s_base[gg];
                const float wg = s_wgt[gg];
                float t2r[Rn];
                #pragma unroll
                for (int r = 0; r < Rn; r++) t2r[r] = s_t2[gg][r];
                const uint4* B2q = (const uint4*)b2b + (size_t)bs * Dn;
                #pragma unroll
                for (int i = 0; i < Dn / 256; i++) {
                    int d = tid + i * 256;
                    uint4 q = B2q[d];
                    float d2 = t2r[0] * bf_lo(q.x) + t2r[1] * bf_hi(q.x)
                             + t2r[2] * bf_lo(q.y) + t2r[3] * bf_hi(q.y)
                             + t2r[4] * bf_lo(q.z) + t2r[5] * bf_hi(q.z)
                             + t2r[6] * bf_lo(q.w) + t2r[7] * bf_hi(q.w);
                    accd[i] += wg * (opre[i] + d2 * SCALE_C);
                }
            }
        }
        __syncthreads();
    }

    #pragma unroll
    for (int i = 0; i < Dn / 256; i++) {
        int d = tid + i * 256;
        O.z[(size_t)b * Dn + d] = s_z[d] + accd[i];
    }
}

// =====================================================================
// launch
// =====================================================================
extern "C" void kernel_launch(void* const* d_in, const int* in_sizes, int n_in,
                              void* d_out, int out_size) {
    const float* z     = (const float*)d_in[0];
    const int*   topk  = (const int*)  d_in[1];
    const int*   cap   = (const int*)  d_in[2];
    const int*   ban   = (const int*)  d_in[3];
    const float* tau   = (const float*)d_in[4];
    const float* eps   = (const float*)d_in[5];
    const float* fc1w  = (const float*)d_in[6];
    const float* fc1b  = (const float*)d_in[7];
    const float* fc2w  = (const float*)d_in[8];
    const float* fc2b  = (const float*)d_in[9];
    const float* proto = (const float*)d_in[10];
    const float* ak    = (const float*)d_in[11];
    const float* ebias = (const float*)d_in[12];
    const float* a1    = (const float*)d_in[13];
    const float* b1    = (const float*)d_in[14];
    const float* a2    = (const float*)d_in[15];
    const float* b2    = (const float*)d_in[16];
    float* out = (float*)d_out;

    float *hpre_ptr, *outpre_ptr;
    unsigned *zb, *w1b, *w2b, *hpb, *a1b, *b1b, *a2b, *b2b;
    cudaGetSymbolAddress((void**)&hpre_ptr, g_hpre);
    cudaGetSymbolAddress((void**)&outpre_ptr, g_outpre);
    cudaGetSymbolAddress((void**)&zb,  g_z_bf);
    cudaGetSymbolAddress((void**)&w1b, g_w1_bf);
    cudaGetSymbolAddress((void**)&w2b, g_w2_bf);
    cudaGetSymbolAddress((void**)&hpb, g_hpre_bf);
    cudaGetSymbolAddress((void**)&a1b, g_a1_bf);
    cudaGetSymbolAddress((void**)&b1b, g_b1_bf);
    cudaGetSymbolAddress((void**)&a2b, g_a2_bf);
    cudaGetSymbolAddress((void**)&b2b, g_b2_bf);

    const int gemm_smem = NSTAGE * STG * sizeof(unsigned);  // 61440
    cudaFuncSetAttribute((const void*)gemm_fused_kernel<1, 1, 32>,
                         cudaFuncAttributeMaxDynamicSharedMemorySize, gemm_smem);
    cudaFuncSetAttribute((const void*)gemm_fused_kernel<0, 2, 16>,
                         cudaFuncAttributeMaxDynamicSharedMemorySize, gemm_smem);

    // 0) one-time fp32 -> bf16 conversion
    convert_kernel<<<2048, 256>>>(z, fc1w, fc2w, a1, b1, a2, b2);

    // 1) h_pre = silu(z @ fc1_w^T + fc1_b) (+ bf16 copy) + logits side work
    gemm_fused_kernel<1, 1, 32><<<dim3(48, 16), 256, gemm_smem>>>(
        (const unsigned short*)zb, (const unsigned short*)w1b, fc1b,
        hpre_ptr, hpb, Bn, Hn, Dn,
        z, proto, ebias, topk, ban, tau, eps, cap, out);

    // 2) out_pre = h_pre @ fc2_w^T + fc2_b + router side block
    gemm_fused_kernel<0, 2, 16><<<dim3(17, 16), 256, gemm_smem>>>(
        (const unsigned short*)hpb, (const unsigned short*)w2b, fc2b,
        outpre_ptr, nullptr, Bn, Dn, Hn,
        z, proto, ebias, topk, ban, tau, eps, cap, out);

    // 3) adapter select + LoRA deltas + final combine
    adapter_kernel<<<Bn, 256>>>(z, ak, a1b, b1b, a2b, b2b, topk, out);
}